// round 11
// baseline (speedup 1.0000x reference)
#include <cuda_runtime.h>
#include <cuda_fp16.h>
#include <cstdint>

#define HIDN  4096
#define NBATCH 2
#define SEQL  2048
#define NHEAD 32
#define NKVH  8
#define DHEAD 128
#define NTOK  (NBATCH * SEQL)
#define KDIM  4096

// ---------------------------------------------------------------------------
// Device scratch (allocation-free rule)
// ---------------------------------------------------------------------------
__device__ __half g_Xhi[(size_t)NTOK * KDIM];
__device__ __half g_Xlo[(size_t)NTOK * KDIM];
__device__ __half g_Wqh[(size_t)HIDN * KDIM];
__device__ __half g_Wkh[(size_t)NKVH * DHEAD * KDIM];
__device__ __half g_Wvh[(size_t)NKVH * DHEAD * KDIM];
__device__ __half g_Woh[(size_t)HIDN * KDIM];
// Q,K,V fp16 — [b, head, s, d]
__device__ __half g_Qh[(size_t)NBATCH * NHEAD * SEQL * DHEAD];
__device__ __half g_Kh2[(size_t)NBATCH * NKVH * SEQL * DHEAD];
__device__ __half g_Vh2[(size_t)NBATCH * NKVH * SEQL * DHEAD];
// attention output [t, hid], fp16 (o-proj input)
__device__ __half g_Ahi[(size_t)NTOK * KDIM];

// ---------------------------------------------------------------------------
// PTX helpers (sm_80-era, safe at compute_103)
// ---------------------------------------------------------------------------
__device__ __forceinline__ uint32_t smem_u32(const void* p) {
    uint32_t r;
    asm("{ .reg .u64 t; cvta.to.shared.u64 t, %1; cvt.u32.u64 %0, t; }"
        : "=r"(r) : "l"(p));
    return r;
}

#define CP16(dst, src) \
    asm volatile("cp.async.cg.shared.global [%0], [%1], 16;" \
                 :: "r"(dst), "l"(src) : "memory")
#define CP_COMMIT() asm volatile("cp.async.commit_group;" ::: "memory")
#define CP_WAIT(n)  asm volatile("cp.async.wait_group %0;" :: "n"(n) : "memory")

__device__ __forceinline__ void ldsm4(uint32_t& r0, uint32_t& r1,
                                      uint32_t& r2, uint32_t& r3, uint32_t a) {
    asm volatile("ldmatrix.sync.aligned.m8n8.x4.shared.b16 {%0,%1,%2,%3}, [%4];"
                 : "=r"(r0), "=r"(r1), "=r"(r2), "=r"(r3) : "r"(a));
}
__device__ __forceinline__ void ldsm4t(uint32_t& r0, uint32_t& r1,
                                       uint32_t& r2, uint32_t& r3, uint32_t a) {
    asm volatile("ldmatrix.sync.aligned.m8n8.x4.trans.shared.b16 {%0,%1,%2,%3}, [%4];"
                 : "=r"(r0), "=r"(r1), "=r"(r2), "=r"(r3) : "r"(a));
}

__device__ __forceinline__ void mma16816(float* c, const uint32_t* a,
                                         uint32_t b0, uint32_t b1) {
    asm volatile(
        "mma.sync.aligned.m16n8k16.row.col.f32.f16.f16.f32 "
        "{%0,%1,%2,%3}, {%4,%5,%6,%7}, {%8,%9}, {%0,%1,%2,%3};"
        : "+f"(c[0]), "+f"(c[1]), "+f"(c[2]), "+f"(c[3])
        : "r"(a[0]), "r"(a[1]), "r"(a[2]), "r"(a[3]), "r"(b0), "r"(b1));
}

// ---------------------------------------------------------------------------
// fp32 -> fp16 splits
// ---------------------------------------------------------------------------
__global__ void split_f32(const float* __restrict__ in, __half* __restrict__ hi,
                          __half* __restrict__ lo, int n4, float scale)
{
    const int stride = gridDim.x * blockDim.x;
    for (int i = blockIdx.x * blockDim.x + threadIdx.x; i < n4; i += stride) {
        float4 v = ((const float4*)in)[i];
        v.x *= scale; v.y *= scale; v.z *= scale; v.w *= scale;
        __half hx = __float2half_rn(v.x), hy = __float2half_rn(v.y);
        __half hz = __float2half_rn(v.z), hw = __float2half_rn(v.w);
        __half lx = __float2half_rn(v.x - __half2float(hx));
        __half ly = __float2half_rn(v.y - __half2float(hy));
        __half lz = __float2half_rn(v.z - __half2float(hz));
        __half lw = __float2half_rn(v.w - __half2float(hw));
        __half2 h01 = __halves2half2(hx, hy), h23 = __halves2half2(hz, hw);
        __half2 l01 = __halves2half2(lx, ly), l23 = __halves2half2(lz, lw);
        uint2 hp, lp;
        hp.x = *(uint32_t*)&h01; hp.y = *(uint32_t*)&h23;
        lp.x = *(uint32_t*)&l01; lp.y = *(uint32_t*)&l23;
        ((uint2*)hi)[i] = hp;
        ((uint2*)lo)[i] = lp;
    }
}

// All four weight matrices, hi-only, one launch.
#define QW4 ((HIDN * KDIM) / 4)
#define KW4 ((NKVH * DHEAD * KDIM) / 4)
#define TOTW4 (QW4 + KW4 + KW4 + QW4)

__global__ void split_weights(const float* __restrict__ q_w,
                              const float* __restrict__ k_w,
                              const float* __restrict__ v_w,
                              const float* __restrict__ o_w,
                              __half* __restrict__ wqh,
                              __half* __restrict__ wkh,
                              __half* __restrict__ wvh,
                              __half* __restrict__ woh, float scale)
{
    const int stride = gridDim.x * blockDim.x;
    for (int i = blockIdx.x * blockDim.x + threadIdx.x; i < TOTW4; i += stride) {
        const float* src;
        __half* hi;
        int j = i;
        if (j < QW4) { src = q_w; hi = wqh; }
        else if ((j -= QW4) < KW4) { src = k_w; hi = wkh; }
        else if ((j -= KW4) < KW4) { src = v_w; hi = wvh; }
        else { j -= KW4; src = o_w; hi = woh; }

        float4 v = ((const float4*)src)[j];
        __half2 h01 = __floats2half2_rn(v.x * scale, v.y * scale);
        __half2 h23 = __floats2half2_rn(v.z * scale, v.w * scale);
        uint2 hp;
        hp.x = *(uint32_t*)&h01; hp.y = *(uint32_t*)&h23;
        ((uint2*)hi)[j] = hp;
    }
}

// ---------------------------------------------------------------------------
// HMMA NT GEMM body (unchanged from R10)
// ---------------------------------------------------------------------------
#define TSZ   16384
#define IWS_C (1.0f / 1024.0f)

template <int SPLIT>
__device__ __forceinline__
void gemm_body(int bx, int by,
               const __half* __restrict__ Ahi, const __half* __restrict__ Alo,
               const __half* __restrict__ Bhi,
               const float* __restrict__ bias, float* __restrict__ C,
               __half* __restrict__ Chi,
               int N, int mode, int nheads, float outscale)
{
    extern __shared__ __align__(1024) char sm[];
    constexpr int NT   = SPLIT + 1;
    constexpr int BOFF = (SPLIT >= 2) ? 2 : 1;
    const int tid  = threadIdx.x;
    const int wid  = tid >> 5;
    const int lane = tid & 31;
    const int m0 = by * 128;
    const int n0 = bx * 128;
    const int wm = (wid >> 2) * 64;
    const int wn = (wid & 3) * 32;
    const uint32_t sbase = smem_u32(sm);

    const __half* Ah = Ahi + (size_t)m0 * KDIM;
    const __half* Al = (SPLIT >= 2) ? (Alo + (size_t)m0 * KDIM) : nullptr;
    const __half* Bh = Bhi + (size_t)n0 * KDIM;

    float acc[4][4][4];
#pragma unroll
    for (int i = 0; i < 4; i++)
#pragma unroll
        for (int j = 0; j < 4; j++)
#pragma unroll
            for (int k = 0; k < 4; k++) acc[i][j][k] = 0.0f;

    auto load_stage = [&](int s, int k0) {
        const uint32_t base = sbase + s * NT * TSZ;
#pragma unroll
        for (int i = 0; i < 4; i++) {
            const int idx = tid + i * 256;
            const int r = idx >> 3, c = idx & 7;
            const uint32_t dst = r * 128 + (((uint32_t)(c ^ (r & 7))) << 4);
            const size_t src = (size_t)r * KDIM + k0 + c * 8;
            CP16(base + dst, (const char*)(Ah + src));
            if (SPLIT >= 2)
                CP16(base + TSZ + dst, (const char*)(Al + src));
            CP16(base + BOFF * TSZ + dst, (const char*)(Bh + src));
        }
        CP_COMMIT();
    };

    load_stage(0, 0);

    const int NIT = KDIM / 64;
    for (int it = 0; it < NIT; ++it) {
        if (it + 1 < NIT) load_stage((it + 1) & 1, (it + 1) * 64);
        if (it + 1 < NIT) { CP_WAIT(1); } else { CP_WAIT(0); }
        __syncthreads();

        const uint32_t stg = sbase + (it & 1) * NT * TSZ;
        const uint32_t sAh = stg, sAl = stg + TSZ;
        const uint32_t sBh = stg + BOFF * TSZ;

        uint32_t bh[4][4];
#pragma unroll
        for (int k16 = 0; k16 < 4; ++k16) {
            if ((k16 & 1) == 0) {
#pragma unroll
                for (int nt = 0; nt < 4; ++nt) {
                    const int r = wn + nt * 8 + (lane & 7);
                    const int c = k16 * 2 + (lane >> 3);
                    const uint32_t off = r * 128 + (((uint32_t)(c ^ (r & 7))) << 4);
                    ldsm4(bh[nt][0], bh[nt][1], bh[nt][2], bh[nt][3], sBh + off);
                }
            }
            const int bo = (k16 & 1) * 2;

            uint32_t ah[4][4], al[4][4];
#pragma unroll
            for (int mt = 0; mt < 4; ++mt) {
                const int r = wm + mt * 16 + (lane & 15);
                const int c = k16 * 2 + (lane >> 4);
                const uint32_t off = r * 128 + (((uint32_t)(c ^ (r & 7))) << 4);
                ldsm4(ah[mt][0], ah[mt][1], ah[mt][2], ah[mt][3], sAh + off);
                if (SPLIT >= 2)
                    ldsm4(al[mt][0], al[mt][1], al[mt][2], al[mt][3], sAl + off);
            }
#pragma unroll
            for (int mt = 0; mt < 4; ++mt)
#pragma unroll
                for (int nt = 0; nt < 4; ++nt) {
                    mma16816(acc[mt][nt], ah[mt], bh[nt][bo], bh[nt][bo + 1]);
                    if (SPLIT >= 2)
                        mma16816(acc[mt][nt], al[mt], bh[nt][bo], bh[nt][bo + 1]);
                }
        }
        __syncthreads();
    }

#pragma unroll
    for (int mt = 0; mt < 4; ++mt) {
#pragma unroll
        for (int nt = 0; nt < 4; ++nt) {
            const int o = n0 + wn + nt * 8 + 2 * (lane & 3);
            const float b0 = bias[o], b1 = bias[o + 1];
#pragma unroll
            for (int half = 0; half < 2; ++half) {
                const int t = m0 + wm + mt * 16 + (lane >> 2) + half * 8;
                float vx = acc[mt][nt][half * 2 + 0] * outscale + b0;
                float vy = acc[mt][nt][half * 2 + 1] * outscale + b1;
                if (mode == 0) {
                    const int bb = t >> 11, s = t & 2047;
                    const int hh = o >> 7, d = o & 127;
                    const size_t idx =
                        (((size_t)(bb * nheads + hh)) * SEQL + s) * DHEAD + d;
                    *(__half2*)&Chi[idx] = __floats2half2_rn(vx, vy);
                } else {
                    float2 v; v.x = vx; v.y = vy;
                    *(float2*)&C[(size_t)t * N + o] = v;
                }
            }
        }
    }
}

__global__ __launch_bounds__(256, 1)
void qkv_proj(const __half* __restrict__ xh, const __half* __restrict__ xl,
              const __half* __restrict__ wqh, const __half* __restrict__ wkh,
              const __half* __restrict__ wvh,
              const float* __restrict__ q_b, const float* __restrict__ k_b,
              const float* __restrict__ v_b,
              __half* __restrict__ qh, __half* __restrict__ kh,
              __half* __restrict__ vh)
{
    const int bx = blockIdx.x;
    if (bx < 32) {
        gemm_body<2>(bx, blockIdx.y, xh, xl, wqh, q_b, nullptr,
                     qh, HIDN, 0, NHEAD, IWS_C);
    } else if (bx < 40) {
        gemm_body<2>(bx - 32, blockIdx.y, xh, xl, wkh, k_b, nullptr,
                     kh, NKVH * DHEAD, 0, NKVH, IWS_C);
    } else {
        gemm_body<2>(bx - 40, blockIdx.y, xh, xl, wvh, v_b, nullptr,
                     vh, NKVH * DHEAD, 0, NKVH, IWS_C);
    }
}

__global__ __launch_bounds__(256, 1)
void o_proj(const __half* __restrict__ ah,
            const __half* __restrict__ woh, const float* __restrict__ o_b,
            float* __restrict__ out)
{
    gemm_body<1>(blockIdx.x, blockIdx.y, ah, nullptr, woh, o_b, out,
                 nullptr, HIDN, 1, 0, IWS_C);
}

// ---------------------------------------------------------------------------
// HMMA causal flash attention — tile-pipelined:
// QK(j+1) issued BEFORE softmax(j) so tensor-pipe overlaps ALU/MUFU.
// 3-stage KV ring; arithmetic per element identical to R10.
// ---------------------------------------------------------------------------
#define FA_QT    32768
#define FA_KVT   16384
#define FA_STG   (2 * FA_KVT)               // 32768 {Kh, Vh}
#define FA_SMEM  (FA_QT + 3 * FA_STG)       // 131072

__global__ __launch_bounds__(256, 1)
void flash_hmma(const __half* __restrict__ Qh_,
                const __half* __restrict__ Kh_,
                const __half* __restrict__ Vh_,
                __half* __restrict__ Ohi)
{
    extern __shared__ __align__(1024) char sm[];
    const uint32_t sb  = smem_u32(sm);
    const uint32_t sQh = sb;
    const uint32_t sKV = sb + FA_QT;

    const int tid = threadIdx.x, wid = tid >> 5, lane = tid & 31;
    const int qb = gridDim.x - 1 - blockIdx.x;
    const int q0 = qb * 128;
    const int h = blockIdx.y, b = blockIdx.z, kvh = h & 7;
    const int wq = wid * 16;
    const float scale = 0.08838834764831845f;

    const size_t qbase  = (((size_t)(b * NHEAD + h))  * SEQL + q0) * DHEAD;
    const size_t kvbase = (((size_t)(b * NKVH + kvh)) * SEQL) * DHEAD;

    auto load_kv = [&](int j, int s) {
        const uint32_t st = sKV + s * FA_STG;
        const size_t base = kvbase + (size_t)j * 64 * DHEAD;
#pragma unroll
        for (int i = 0; i < 4; i++) {
            const int idx = tid + i * 256;
            const int r = idx >> 4, c = idx & 15;
            const uint32_t dst = r * 256 + (((uint32_t)(c ^ (r & 7))) << 4);
            const size_t src = base + (size_t)r * DHEAD + c * 8;
            CP16(st + dst,          (const char*)(Kh_ + src));
            CP16(st + FA_KVT + dst, (const char*)(Vh_ + src));
        }
    };

    // Warp-level QK^T for one KV tile into S[8][4]
    auto compute_qk = [&](float (&S)[8][4], uint32_t st) {
#pragma unroll
        for (int nt = 0; nt < 8; nt++)
#pragma unroll
            for (int k = 0; k < 4; k++) S[nt][k] = 0.0f;
#pragma unroll
        for (int kp = 0; kp < 4; kp++) {
            uint32_t ah[2][4];
#pragma unroll
            for (int x = 0; x < 2; x++) {
                const int ks = kp * 2 + x;
                const int r = wq + (lane & 15);
                const int c = ks * 2 + (lane >> 4);
                const uint32_t off = r * 256 + (((uint32_t)(c ^ (r & 7))) << 4);
                ldsm4(ah[x][0], ah[x][1], ah[x][2], ah[x][3], sQh + off);
            }
#pragma unroll
            for (int nt = 0; nt < 8; nt++) {
                const int r = nt * 8 + (lane & 7);
                const int c = kp * 4 + (lane >> 3);
                const uint32_t off = r * 256 + (((uint32_t)(c ^ (r & 7))) << 4);
                uint32_t kh[4];
                ldsm4(kh[0], kh[1], kh[2], kh[3], st + off);
                mma16816(S[nt], ah[0], kh[0], kh[1]);
                mma16816(S[nt], ah[1], kh[2], kh[3]);
            }
        }
    };

    // Prologue: Q + KV(0) (group 0), KV(1) (group 1)   [njt >= 2 always]
#pragma unroll
    for (int i = 0; i < 8; i++) {
        const int idx = tid + i * 256;
        const int r = idx >> 4, c = idx & 15;
        const uint32_t dst = r * 256 + (((uint32_t)(c ^ (r & 7))) << 4);
        CP16(sQh + dst, (const char*)(Qh_ + qbase + (size_t)r * DHEAD + c * 8));
    }
    load_kv(0, 0);
    CP_COMMIT();
    const int njt = (q0 + 128) / 64;
    load_kv(1, 1);
    CP_COMMIT();
    CP_WAIT(1);
    __syncthreads();

    float O[16][4];
#pragma unroll
    for (int i = 0; i < 16; i++)
#pragma unroll
        for (int k = 0; k < 4; k++) O[i][k] = 0.0f;
    float m0 = -1e30f, m1 = -1e30f, l0 = 0.0f, l1 = 0.0f;

    float Scur[8][4];
    compute_qk(Scur, sKV);                 // S(0), stage 0 (all warps active at j=0)

    for (int j = 0; j < njt; j++) {
        __syncthreads();                   // PV(j-1) readers done before overwrite
        if (j + 2 < njt) {
            load_kv(j + 2, (j + 2) % 3);
            CP_COMMIT();
            CP_WAIT(1);                    // KV(j+1) complete
        } else {
            CP_WAIT(0);
        }
        __syncthreads();                   // KV(j+1) visible

        const int row_hi = q0 + wq + 15;

        // --- QK for next tile FIRST (tensor pipe fills while softmax runs) ---
        float Snext[8][4];
        const bool act_next = (j + 1 < njt) && (row_hi >= (j + 1) * 64);
        if (act_next)
            compute_qk(Snext, sKV + ((j + 1) % 3) * FA_STG);

        const int j0 = j * 64;
        if (row_hi >= j0) {
            const uint32_t st = sKV + (j % 3) * FA_STG;

            // ---- causal mask on current tile ----
            if (j0 + 63 > q0 + wq) {
                const int row0 = q0 + wq + (lane >> 2), row1 = row0 + 8;
#pragma unroll
                for (int nt = 0; nt < 8; nt++) {
                    const int cb = j0 + nt * 8 + 2 * (lane & 3);
                    if (cb     > row0) Scur[nt][0] = -1e30f;
                    if (cb + 1 > row0) Scur[nt][1] = -1e30f;
                    if (cb     > row1) Scur[nt][2] = -1e30f;
                    if (cb + 1 > row1) Scur[nt][3] = -1e30f;
                }
            }

            // ---- online softmax ----
            float tm0 = -1e30f, tm1 = -1e30f;
#pragma unroll
            for (int nt = 0; nt < 8; nt++) {
                tm0 = fmaxf(tm0, fmaxf(Scur[nt][0], Scur[nt][1]));
                tm1 = fmaxf(tm1, fmaxf(Scur[nt][2], Scur[nt][3]));
            }
            tm0 = fmaxf(tm0, __shfl_xor_sync(0xffffffffu, tm0, 1));
            tm0 = fmaxf(tm0, __shfl_xor_sync(0xffffffffu, tm0, 2));
            tm1 = fmaxf(tm1, __shfl_xor_sync(0xffffffffu, tm1, 1));
            tm1 = fmaxf(tm1, __shfl_xor_sync(0xffffffffu, tm1, 2));
            const float mn0 = fmaxf(m0, tm0), mn1 = fmaxf(m1, tm1);
            const float cr0 = __expf((m0 - mn0) * scale);
            const float cr1 = __expf((m1 - mn1) * scale);
            m0 = mn0; m1 = mn1;

            uint32_t ph[8][2], pl[8][2];
            float ps0 = 0.0f, ps1 = 0.0f;
#pragma unroll
            for (int nt = 0; nt < 8; nt++) {
                const float p0 = __expf((Scur[nt][0] - mn0) * scale);
                const float p1 = __expf((Scur[nt][1] - mn0) * scale);
                const float p2 = __expf((Scur[nt][2] - mn1) * scale);
                const float p3 = __expf((Scur[nt][3] - mn1) * scale);
                ps0 += p0 + p1;  ps1 += p2 + p3;
                const __half h0 = __float2half_rn(p0), h1 = __float2half_rn(p1);
                const __half h2 = __float2half_rn(p2), h3 = __float2half_rn(p3);
                const __half e0 = __float2half_rn(p0 - __half2float(h0));
                const __half e1 = __float2half_rn(p1 - __half2float(h1));
                const __half e2 = __float2half_rn(p2 - __half2float(h2));
                const __half e3 = __float2half_rn(p3 - __half2float(h3));
                __half2 a01 = __halves2half2(h0, h1), a23 = __halves2half2(h2, h3);
                __half2 b01 = __halves2half2(e0, e1), b23 = __halves2half2(e2, e3);
                ph[nt][0] = *(uint32_t*)&a01;  ph[nt][1] = *(uint32_t*)&a23;
                pl[nt][0] = *(uint32_t*)&b01;  pl[nt][1] = *(uint32_t*)&b23;
            }
            ps0 += __shfl_xor_sync(0xffffffffu, ps0, 1);
            ps0 += __shfl_xor_sync(0xffffffffu, ps0, 2);
            ps1 += __shfl_xor_sync(0xffffffffu, ps1, 1);
            ps1 += __shfl_xor_sync(0xffffffffu, ps1, 2);
            l0 = l0 * cr0 + ps0;
            l1 = l1 * cr1 + ps1;
#pragma unroll
            for (int nt = 0; nt < 16; nt++) {
                O[nt][0] *= cr0; O[nt][1] *= cr0;
                O[nt][2] *= cr1; O[nt][3] *= cr1;
            }

            // ---- PV (P exact via Ph+Pl) ----
#pragma unroll
            for (int kt = 0; kt < 4; kt++) {
                uint32_t pah[4], pal[4];
                pah[0] = ph[2 * kt][0];     pah[1] = ph[2 * kt][1];
                pah[2] = ph[2 * kt + 1][0]; pah[3] = ph[2 * kt + 1][1];
                pal[0] = pl[2 * kt][0];     pal[1] = pl[2 * kt][1];
                pal[2] = pl[2 * kt + 1][0]; pal[3] = pl[2 * kt + 1][1];
#pragma unroll
                for (int np = 0; np < 8; np++) {
                    const int r = kt * 16 + (lane & 15);
                    const int c = np * 2 + (lane >> 4);
                    const uint32_t off = r * 256 + (((uint32_t)(c ^ (r & 7))) << 4);
                    uint32_t vh[4];
                    ldsm4t(vh[0], vh[1], vh[2], vh[3], st + FA_KVT + off);
                    mma16816(O[2 * np],     pah, vh[0], vh[1]);
                    mma16816(O[2 * np],     pal, vh[0], vh[1]);
                    mma16816(O[2 * np + 1], pah, vh[2], vh[3]);
                    mma16816(O[2 * np + 1], pal, vh[2], vh[3]);
                }
            }
        }

        // rotate S buffers (garbage if !act_next — next iter guards on cond)
#pragma unroll
        for (int nt = 0; nt < 8; nt++)
#pragma unroll
            for (int k = 0; k < 4; k++) Scur[nt][k] = Snext[nt][k];
    }

    const float i0 = 1.0f / l0, i1 = 1.0f / l1;
    const int t0 = b * SEQL + q0 + wq + (lane >> 2);
#pragma unroll
    for (int nt = 0; nt < 16; nt++) {
        const int col = h * DHEAD + nt * 8 + 2 * (lane & 3);
        *(__half2*)&Ohi[(size_t)t0 * KDIM + col] =
            __floats2half2_rn(O[nt][0] * i0, O[nt][1] * i0);
        *(__half2*)&Ohi[(size_t)(t0 + 8) * KDIM + col] =
            __floats2half2_rn(O[nt][2] * i1, O[nt][3] * i1);
    }
}

// ---------------------------------------------------------------------------
extern "C" void kernel_launch(void* const* d_in, const int* in_sizes, int n_in,
                              void* d_out, int out_size)
{
    const float* x   = (const float*)d_in[0];
    // d_in[1] = mask: causal structure applied analytically, not read.
    const float* q_w = (const float*)d_in[2];
    const float* q_b = (const float*)d_in[3];
    const float* k_w = (const float*)d_in[4];
    const float* k_b = (const float*)d_in[5];
    const float* v_w = (const float*)d_in[6];
    const float* v_b = (const float*)d_in[7];
    const float* o_w = (const float*)d_in[8];
    const float* o_b = (const float*)d_in[9];
    float* out = (float*)d_out;

    __half *xh, *xl, *wqh, *wkh, *wvh, *woh;
    __half *qh, *kh, *vh, *ah;
    cudaGetSymbolAddress((void**)&xh, g_Xhi);   cudaGetSymbolAddress((void**)&xl, g_Xlo);
    cudaGetSymbolAddress((void**)&wqh, g_Wqh);
    cudaGetSymbolAddress((void**)&wkh, g_Wkh);
    cudaGetSymbolAddress((void**)&wvh, g_Wvh);
    cudaGetSymbolAddress((void**)&woh, g_Woh);
    cudaGetSymbolAddress((void**)&qh, g_Qh);
    cudaGetSymbolAddress((void**)&kh, g_Kh2);
    cudaGetSymbolAddress((void**)&vh, g_Vh2);
    cudaGetSymbolAddress((void**)&ah, g_Ahi);

    cudaFuncSetAttribute(qkv_proj, cudaFuncAttributeMaxDynamicSharedMemorySize,
                         2 * 3 * TSZ);                     // 98304 (split-2)
    cudaFuncSetAttribute(o_proj, cudaFuncAttributeMaxDynamicSharedMemorySize,
                         2 * 2 * TSZ);                     // 65536
    cudaFuncSetAttribute(flash_hmma, cudaFuncAttributeMaxDynamicSharedMemorySize,
                         FA_SMEM);

    const float WS = 1024.0f;
    dim3 blk(256);

    // Splits
    split_f32<<<1024, 256>>>(x, xh, xl, (NTOK * KDIM) / 4, 1.0f);
    split_weights<<<1024, 256>>>(q_w, k_w, v_w, o_w, wqh, wkh, wvh, woh, WS);

    // Fused Q/K/V projections (all split-2)
    qkv_proj<<<dim3(48, 32), blk, 2 * 3 * TSZ>>>(xh, xl, wqh, wkh, wvh,
                                                 q_b, k_b, v_b, qh, kh, vh);

    // Attention (tile-pipelined)
    flash_hmma<<<dim3(SEQL / 128, NHEAD, NBATCH), blk, FA_SMEM>>>(qh, kh, vh, ah);

    // Output projection (pure fp16)
    o_proj<<<dim3(32, 32), blk, 2 * 2 * TSZ>>>(ah, woh, o_b, out);
}

// round 12
// speedup vs baseline: 1.0571x; 1.0571x over previous
#include <cuda_runtime.h>
#include <cuda_fp16.h>
#include <cstdint>

#define HIDN  4096
#define NBATCH 2
#define SEQL  2048
#define NHEAD 32
#define NKVH  8
#define DHEAD 128
#define NTOK  (NBATCH * SEQL)
#define KDIM  4096

// ---------------------------------------------------------------------------
// Device scratch (allocation-free rule)
// ---------------------------------------------------------------------------
__device__ __half g_Xhi[(size_t)NTOK * KDIM];
__device__ __half g_Xlo[(size_t)NTOK * KDIM];
__device__ __half g_Wqh[(size_t)HIDN * KDIM];
__device__ __half g_Wkh[(size_t)NKVH * DHEAD * KDIM];
__device__ __half g_Wvh[(size_t)NKVH * DHEAD * KDIM];
__device__ __half g_Woh[(size_t)HIDN * KDIM];
// Q,K,V fp16 — [b, head, s, d]
__device__ __half g_Qh[(size_t)NBATCH * NHEAD * SEQL * DHEAD];
__device__ __half g_Kh2[(size_t)NBATCH * NKVH * SEQL * DHEAD];
__device__ __half g_Vh2[(size_t)NBATCH * NKVH * SEQL * DHEAD];
// attention output [t, hid], fp16 (o-proj input)
__device__ __half g_Ahi[(size_t)NTOK * KDIM];

// ---------------------------------------------------------------------------
// PTX helpers (sm_80-era, safe at compute_103)
// ---------------------------------------------------------------------------
__device__ __forceinline__ uint32_t smem_u32(const void* p) {
    uint32_t r;
    asm("{ .reg .u64 t; cvta.to.shared.u64 t, %1; cvt.u32.u64 %0, t; }"
        : "=r"(r) : "l"(p));
    return r;
}

#define CP16(dst, src) \
    asm volatile("cp.async.cg.shared.global [%0], [%1], 16;" \
                 :: "r"(dst), "l"(src) : "memory")
#define CP_COMMIT() asm volatile("cp.async.commit_group;" ::: "memory")
#define CP_WAIT(n)  asm volatile("cp.async.wait_group %0;" :: "n"(n) : "memory")

__device__ __forceinline__ void ldsm4(uint32_t& r0, uint32_t& r1,
                                      uint32_t& r2, uint32_t& r3, uint32_t a) {
    asm volatile("ldmatrix.sync.aligned.m8n8.x4.shared.b16 {%0,%1,%2,%3}, [%4];"
                 : "=r"(r0), "=r"(r1), "=r"(r2), "=r"(r3) : "r"(a));
}
__device__ __forceinline__ void ldsm4t(uint32_t& r0, uint32_t& r1,
                                       uint32_t& r2, uint32_t& r3, uint32_t a) {
    asm volatile("ldmatrix.sync.aligned.m8n8.x4.trans.shared.b16 {%0,%1,%2,%3}, [%4];"
                 : "=r"(r0), "=r"(r1), "=r"(r2), "=r"(r3) : "r"(a));
}

__device__ __forceinline__ void mma16816(float* c, const uint32_t* a,
                                         uint32_t b0, uint32_t b1) {
    asm volatile(
        "mma.sync.aligned.m16n8k16.row.col.f32.f16.f16.f32 "
        "{%0,%1,%2,%3}, {%4,%5,%6,%7}, {%8,%9}, {%0,%1,%2,%3};"
        : "+f"(c[0]), "+f"(c[1]), "+f"(c[2]), "+f"(c[3])
        : "r"(a[0]), "r"(a[1]), "r"(a[2]), "r"(a[3]), "r"(b0), "r"(b1));
}

// ---------------------------------------------------------------------------
// fp32 -> fp16 splits
// ---------------------------------------------------------------------------
__global__ void split_f32(const float* __restrict__ in, __half* __restrict__ hi,
                          __half* __restrict__ lo, int n4, float scale)
{
    const int stride = gridDim.x * blockDim.x;
    for (int i = blockIdx.x * blockDim.x + threadIdx.x; i < n4; i += stride) {
        float4 v = ((const float4*)in)[i];
        v.x *= scale; v.y *= scale; v.z *= scale; v.w *= scale;
        __half hx = __float2half_rn(v.x), hy = __float2half_rn(v.y);
        __half hz = __float2half_rn(v.z), hw = __float2half_rn(v.w);
        __half lx = __float2half_rn(v.x - __half2float(hx));
        __half ly = __float2half_rn(v.y - __half2float(hy));
        __half lz = __float2half_rn(v.z - __half2float(hz));
        __half lw = __float2half_rn(v.w - __half2float(hw));
        __half2 h01 = __halves2half2(hx, hy), h23 = __halves2half2(hz, hw);
        __half2 l01 = __halves2half2(lx, ly), l23 = __halves2half2(lz, lw);
        uint2 hp, lp;
        hp.x = *(uint32_t*)&h01; hp.y = *(uint32_t*)&h23;
        lp.x = *(uint32_t*)&l01; lp.y = *(uint32_t*)&l23;
        ((uint2*)hi)[i] = hp;
        ((uint2*)lo)[i] = lp;
    }
}

// All four weight matrices, hi-only, one launch.
#define QW4 ((HIDN * KDIM) / 4)
#define KW4 ((NKVH * DHEAD * KDIM) / 4)
#define TOTW4 (QW4 + KW4 + KW4 + QW4)

__global__ void split_weights(const float* __restrict__ q_w,
                              const float* __restrict__ k_w,
                              const float* __restrict__ v_w,
                              const float* __restrict__ o_w,
                              __half* __restrict__ wqh,
                              __half* __restrict__ wkh,
                              __half* __restrict__ wvh,
                              __half* __restrict__ woh, float scale)
{
    const int stride = gridDim.x * blockDim.x;
    for (int i = blockIdx.x * blockDim.x + threadIdx.x; i < TOTW4; i += stride) {
        const float* src;
        __half* hi;
        int j = i;
        if (j < QW4) { src = q_w; hi = wqh; }
        else if ((j -= QW4) < KW4) { src = k_w; hi = wkh; }
        else if ((j -= KW4) < KW4) { src = v_w; hi = wvh; }
        else { j -= KW4; src = o_w; hi = woh; }

        float4 v = ((const float4*)src)[j];
        __half2 h01 = __floats2half2_rn(v.x * scale, v.y * scale);
        __half2 h23 = __floats2half2_rn(v.z * scale, v.w * scale);
        uint2 hp;
        hp.x = *(uint32_t*)&h01; hp.y = *(uint32_t*)&h23;
        ((uint2*)hi)[j] = hp;
    }
}

// ---------------------------------------------------------------------------
// HMMA NT GEMM body (unchanged from R10)
// ---------------------------------------------------------------------------
#define TSZ   16384
#define IWS_C (1.0f / 1024.0f)

template <int SPLIT>
__device__ __forceinline__
void gemm_body(int bx, int by,
               const __half* __restrict__ Ahi, const __half* __restrict__ Alo,
               const __half* __restrict__ Bhi,
               const float* __restrict__ bias, float* __restrict__ C,
               __half* __restrict__ Chi,
               int N, int mode, int nheads, float outscale)
{
    extern __shared__ __align__(1024) char sm[];
    constexpr int NT   = SPLIT + 1;
    constexpr int BOFF = (SPLIT >= 2) ? 2 : 1;
    const int tid  = threadIdx.x;
    const int wid  = tid >> 5;
    const int lane = tid & 31;
    const int m0 = by * 128;
    const int n0 = bx * 128;
    const int wm = (wid >> 2) * 64;
    const int wn = (wid & 3) * 32;
    const uint32_t sbase = smem_u32(sm);

    const __half* Ah = Ahi + (size_t)m0 * KDIM;
    const __half* Al = (SPLIT >= 2) ? (Alo + (size_t)m0 * KDIM) : nullptr;
    const __half* Bh = Bhi + (size_t)n0 * KDIM;

    float acc[4][4][4];
#pragma unroll
    for (int i = 0; i < 4; i++)
#pragma unroll
        for (int j = 0; j < 4; j++)
#pragma unroll
            for (int k = 0; k < 4; k++) acc[i][j][k] = 0.0f;

    auto load_stage = [&](int s, int k0) {
        const uint32_t base = sbase + s * NT * TSZ;
#pragma unroll
        for (int i = 0; i < 4; i++) {
            const int idx = tid + i * 256;
            const int r = idx >> 3, c = idx & 7;
            const uint32_t dst = r * 128 + (((uint32_t)(c ^ (r & 7))) << 4);
            const size_t src = (size_t)r * KDIM + k0 + c * 8;
            CP16(base + dst, (const char*)(Ah + src));
            if (SPLIT >= 2)
                CP16(base + TSZ + dst, (const char*)(Al + src));
            CP16(base + BOFF * TSZ + dst, (const char*)(Bh + src));
        }
        CP_COMMIT();
    };

    load_stage(0, 0);

    const int NIT = KDIM / 64;
    for (int it = 0; it < NIT; ++it) {
        if (it + 1 < NIT) load_stage((it + 1) & 1, (it + 1) * 64);
        if (it + 1 < NIT) { CP_WAIT(1); } else { CP_WAIT(0); }
        __syncthreads();

        const uint32_t stg = sbase + (it & 1) * NT * TSZ;
        const uint32_t sAh = stg, sAl = stg + TSZ;
        const uint32_t sBh = stg + BOFF * TSZ;

        uint32_t bh[4][4];
#pragma unroll
        for (int k16 = 0; k16 < 4; ++k16) {
            if ((k16 & 1) == 0) {
#pragma unroll
                for (int nt = 0; nt < 4; ++nt) {
                    const int r = wn + nt * 8 + (lane & 7);
                    const int c = k16 * 2 + (lane >> 3);
                    const uint32_t off = r * 128 + (((uint32_t)(c ^ (r & 7))) << 4);
                    ldsm4(bh[nt][0], bh[nt][1], bh[nt][2], bh[nt][3], sBh + off);
                }
            }
            const int bo = (k16 & 1) * 2;

            uint32_t ah[4][4], al[4][4];
#pragma unroll
            for (int mt = 0; mt < 4; ++mt) {
                const int r = wm + mt * 16 + (lane & 15);
                const int c = k16 * 2 + (lane >> 4);
                const uint32_t off = r * 128 + (((uint32_t)(c ^ (r & 7))) << 4);
                ldsm4(ah[mt][0], ah[mt][1], ah[mt][2], ah[mt][3], sAh + off);
                if (SPLIT >= 2)
                    ldsm4(al[mt][0], al[mt][1], al[mt][2], al[mt][3], sAl + off);
            }
#pragma unroll
            for (int mt = 0; mt < 4; ++mt)
#pragma unroll
                for (int nt = 0; nt < 4; ++nt) {
                    mma16816(acc[mt][nt], ah[mt], bh[nt][bo], bh[nt][bo + 1]);
                    if (SPLIT >= 2)
                        mma16816(acc[mt][nt], al[mt], bh[nt][bo], bh[nt][bo + 1]);
                }
        }
        __syncthreads();
    }

#pragma unroll
    for (int mt = 0; mt < 4; ++mt) {
#pragma unroll
        for (int nt = 0; nt < 4; ++nt) {
            const int o = n0 + wn + nt * 8 + 2 * (lane & 3);
            const float b0 = bias[o], b1 = bias[o + 1];
#pragma unroll
            for (int half = 0; half < 2; ++half) {
                const int t = m0 + wm + mt * 16 + (lane >> 2) + half * 8;
                float vx = acc[mt][nt][half * 2 + 0] * outscale + b0;
                float vy = acc[mt][nt][half * 2 + 1] * outscale + b1;
                if (mode == 0) {
                    const int bb = t >> 11, s = t & 2047;
                    const int hh = o >> 7, d = o & 127;
                    const size_t idx =
                        (((size_t)(bb * nheads + hh)) * SEQL + s) * DHEAD + d;
                    *(__half2*)&Chi[idx] = __floats2half2_rn(vx, vy);
                } else {
                    float2 v; v.x = vx; v.y = vy;
                    *(float2*)&C[(size_t)t * N + o] = v;
                }
            }
        }
    }
}

__global__ __launch_bounds__(256, 1)
void qkv_proj(const __half* __restrict__ xh, const __half* __restrict__ xl,
              const __half* __restrict__ wqh, const __half* __restrict__ wkh,
              const __half* __restrict__ wvh,
              const float* __restrict__ q_b, const float* __restrict__ k_b,
              const float* __restrict__ v_b,
              __half* __restrict__ qh, __half* __restrict__ kh,
              __half* __restrict__ vh)
{
    const int bx = blockIdx.x;
    if (bx < 32) {
        gemm_body<2>(bx, blockIdx.y, xh, xl, wqh, q_b, nullptr,
                     qh, HIDN, 0, NHEAD, IWS_C);
    } else if (bx < 40) {
        gemm_body<2>(bx - 32, blockIdx.y, xh, xl, wkh, k_b, nullptr,
                     kh, NKVH * DHEAD, 0, NKVH, IWS_C);
    } else {
        gemm_body<2>(bx - 40, blockIdx.y, xh, xl, wvh, v_b, nullptr,
                     vh, NKVH * DHEAD, 0, NKVH, IWS_C);
    }
}

__global__ __launch_bounds__(256, 1)
void o_proj(const __half* __restrict__ ah,
            const __half* __restrict__ woh, const float* __restrict__ o_b,
            float* __restrict__ out)
{
    gemm_body<1>(blockIdx.x, blockIdx.y, ah, nullptr, woh, o_b, out,
                 nullptr, HIDN, 1, 0, IWS_C);
}

// ---------------------------------------------------------------------------
// HMMA causal flash attention (R10 structure).
// Q,K,V fp16. PV uses rounded P only; l accumulates the ROUNDED p values so
// the output is an exact weighted average (first-order rounding bias cancels).
// smem: Qh 32KB; 2 stages of {Kh, Vh} 32KB.
// ---------------------------------------------------------------------------
#define FA_QT    32768
#define FA_KVT   16384
#define FA_STG   (2 * FA_KVT)               // 32768
#define FA_SMEM  (FA_QT + 2 * FA_STG)       // 98304

__global__ __launch_bounds__(256, 1)
void flash_hmma(const __half* __restrict__ Qh_,
                const __half* __restrict__ Kh_,
                const __half* __restrict__ Vh_,
                __half* __restrict__ Ohi)
{
    extern __shared__ __align__(1024) char sm[];
    const uint32_t sb  = smem_u32(sm);
    const uint32_t sQh = sb;
    const uint32_t sKV = sb + FA_QT;

    const int tid = threadIdx.x, wid = tid >> 5, lane = tid & 31;
    const int qb = gridDim.x - 1 - blockIdx.x;
    const int q0 = qb * 128;
    const int h = blockIdx.y, b = blockIdx.z, kvh = h & 7;
    const int wq = wid * 16;
    const float scale = 0.08838834764831845f;

    const size_t qbase  = (((size_t)(b * NHEAD + h))  * SEQL + q0) * DHEAD;
    const size_t kvbase = (((size_t)(b * NKVH + kvh)) * SEQL) * DHEAD;

#pragma unroll
    for (int i = 0; i < 8; i++) {
        const int idx = tid + i * 256;
        const int r = idx >> 4, c = idx & 15;
        const uint32_t dst = r * 256 + (((uint32_t)(c ^ (r & 7))) << 4);
        CP16(sQh + dst, (const char*)(Qh_ + qbase + (size_t)r * DHEAD + c * 8));
    }
    auto load_kv = [&](int j, int s) {
        const uint32_t st = sKV + s * FA_STG;
        const size_t base = kvbase + (size_t)j * 64 * DHEAD;
#pragma unroll
        for (int i = 0; i < 4; i++) {
            const int idx = tid + i * 256;
            const int r = idx >> 4, c = idx & 15;
            const uint32_t dst = r * 256 + (((uint32_t)(c ^ (r & 7))) << 4);
            const size_t src = base + (size_t)r * DHEAD + c * 8;
            CP16(st + dst,          (const char*)(Kh_ + src));
            CP16(st + FA_KVT + dst, (const char*)(Vh_ + src));
        }
    };
    load_kv(0, 0);
    CP_COMMIT();

    float O[16][4];
#pragma unroll
    for (int i = 0; i < 16; i++)
#pragma unroll
        for (int k = 0; k < 4; k++) O[i][k] = 0.0f;
    float m0 = -1e30f, m1 = -1e30f, l0 = 0.0f, l1 = 0.0f;

    const int njt = (q0 + 128) / 64;
    for (int j = 0; j < njt; j++) {
        if (j + 1 < njt) { load_kv(j + 1, (j + 1) & 1); CP_COMMIT(); CP_WAIT(1); }
        else             { CP_WAIT(0); }
        __syncthreads();
        const uint32_t st = sKV + (j & 1) * FA_STG;
        const int j0 = j * 64;

        if (q0 + wq + 15 >= j0) {
            float S[8][4];
#pragma unroll
            for (int nt = 0; nt < 8; nt++)
#pragma unroll
                for (int k = 0; k < 4; k++) S[nt][k] = 0.0f;

#pragma unroll
            for (int kp = 0; kp < 4; kp++) {
                uint32_t ah[2][4];
#pragma unroll
                for (int x = 0; x < 2; x++) {
                    const int ks = kp * 2 + x;
                    const int r = wq + (lane & 15);
                    const int c = ks * 2 + (lane >> 4);
                    const uint32_t off = r * 256 + (((uint32_t)(c ^ (r & 7))) << 4);
                    ldsm4(ah[x][0], ah[x][1], ah[x][2], ah[x][3], sQh + off);
                }
#pragma unroll
                for (int nt = 0; nt < 8; nt++) {
                    const int r = nt * 8 + (lane & 7);
                    const int c = kp * 4 + (lane >> 3);
                    const uint32_t off = r * 256 + (((uint32_t)(c ^ (r & 7))) << 4);
                    uint32_t kh[4];
                    ldsm4(kh[0], kh[1], kh[2], kh[3], st + off);
                    mma16816(S[nt], ah[0], kh[0], kh[1]);
                    mma16816(S[nt], ah[1], kh[2], kh[3]);
                }
            }

            if (j0 + 63 > q0 + wq) {
                const int row0 = q0 + wq + (lane >> 2), row1 = row0 + 8;
#pragma unroll
                for (int nt = 0; nt < 8; nt++) {
                    const int cb = j0 + nt * 8 + 2 * (lane & 3);
                    if (cb     > row0) S[nt][0] = -1e30f;
                    if (cb + 1 > row0) S[nt][1] = -1e30f;
                    if (cb     > row1) S[nt][2] = -1e30f;
                    if (cb + 1 > row1) S[nt][3] = -1e30f;
                }
            }

            float tm0 = -1e30f, tm1 = -1e30f;
#pragma unroll
            for (int nt = 0; nt < 8; nt++) {
                tm0 = fmaxf(tm0, fmaxf(S[nt][0], S[nt][1]));
                tm1 = fmaxf(tm1, fmaxf(S[nt][2], S[nt][3]));
            }
            tm0 = fmaxf(tm0, __shfl_xor_sync(0xffffffffu, tm0, 1));
            tm0 = fmaxf(tm0, __shfl_xor_sync(0xffffffffu, tm0, 2));
            tm1 = fmaxf(tm1, __shfl_xor_sync(0xffffffffu, tm1, 1));
            tm1 = fmaxf(tm1, __shfl_xor_sync(0xffffffffu, tm1, 2));
            const float mn0 = fmaxf(m0, tm0), mn1 = fmaxf(m1, tm1);
            const float cr0 = __expf((m0 - mn0) * scale);
            const float cr1 = __expf((m1 - mn1) * scale);
            m0 = mn0; m1 = mn1;

            uint32_t ph[8][2];
            float ps0 = 0.0f, ps1 = 0.0f;
#pragma unroll
            for (int nt = 0; nt < 8; nt++) {
                const float p0 = __expf((S[nt][0] - mn0) * scale);
                const float p1 = __expf((S[nt][1] - mn0) * scale);
                const float p2 = __expf((S[nt][2] - mn1) * scale);
                const float p3 = __expf((S[nt][3] - mn1) * scale);
                const __half h0 = __float2half_rn(p0), h1 = __float2half_rn(p1);
                const __half h2 = __float2half_rn(p2), h3 = __float2half_rn(p3);
                // l accumulates the ROUNDED p (numerator/denominator consistent)
                ps0 += __half2float(h0) + __half2float(h1);
                ps1 += __half2float(h2) + __half2float(h3);
                __half2 a01 = __halves2half2(h0, h1), a23 = __halves2half2(h2, h3);
                ph[nt][0] = *(uint32_t*)&a01;  ph[nt][1] = *(uint32_t*)&a23;
            }
            ps0 += __shfl_xor_sync(0xffffffffu, ps0, 1);
            ps0 += __shfl_xor_sync(0xffffffffu, ps0, 2);
            ps1 += __shfl_xor_sync(0xffffffffu, ps1, 1);
            ps1 += __shfl_xor_sync(0xffffffffu, ps1, 2);
            l0 = l0 * cr0 + ps0;
            l1 = l1 * cr1 + ps1;
#pragma unroll
            for (int nt = 0; nt < 16; nt++) {
                O[nt][0] *= cr0; O[nt][1] *= cr0;
                O[nt][2] *= cr1; O[nt][3] *= cr1;
            }

            // ---- PV: O += round(P) . V ----
#pragma unroll
            for (int kt = 0; kt < 4; kt++) {
                uint32_t pah[4];
                pah[0] = ph[2 * kt][0];     pah[1] = ph[2 * kt][1];
                pah[2] = ph[2 * kt + 1][0]; pah[3] = ph[2 * kt + 1][1];
#pragma unroll
                for (int np = 0; np < 8; np++) {
                    const int r = kt * 16 + (lane & 15);
                    const int c = np * 2 + (lane >> 4);
                    const uint32_t off = r * 256 + (((uint32_t)(c ^ (r & 7))) << 4);
                    uint32_t vh[4];
                    ldsm4t(vh[0], vh[1], vh[2], vh[3], st + FA_KVT + off);
                    mma16816(O[2 * np],     pah, vh[0], vh[1]);
                    mma16816(O[2 * np + 1], pah, vh[2], vh[3]);
                }
            }
        }
        __syncthreads();
    }

    const float i0 = 1.0f / l0, i1 = 1.0f / l1;
    const int t0 = b * SEQL + q0 + wq + (lane >> 2);
#pragma unroll
    for (int nt = 0; nt < 16; nt++) {
        const int col = h * DHEAD + nt * 8 + 2 * (lane & 3);
        *(__half2*)&Ohi[(size_t)t0 * KDIM + col] =
            __floats2half2_rn(O[nt][0] * i0, O[nt][1] * i0);
        *(__half2*)&Ohi[(size_t)(t0 + 8) * KDIM + col] =
            __floats2half2_rn(O[nt][2] * i1, O[nt][3] * i1);
    }
}

// ---------------------------------------------------------------------------
extern "C" void kernel_launch(void* const* d_in, const int* in_sizes, int n_in,
                              void* d_out, int out_size)
{
    const float* x   = (const float*)d_in[0];
    // d_in[1] = mask: causal structure applied analytically, not read.
    const float* q_w = (const float*)d_in[2];
    const float* q_b = (const float*)d_in[3];
    const float* k_w = (const float*)d_in[4];
    const float* k_b = (const float*)d_in[5];
    const float* v_w = (const float*)d_in[6];
    const float* v_b = (const float*)d_in[7];
    const float* o_w = (const float*)d_in[8];
    const float* o_b = (const float*)d_in[9];
    float* out = (float*)d_out;

    __half *xh, *xl, *wqh, *wkh, *wvh, *woh;
    __half *qh, *kh, *vh, *ah;
    cudaGetSymbolAddress((void**)&xh, g_Xhi);   cudaGetSymbolAddress((void**)&xl, g_Xlo);
    cudaGetSymbolAddress((void**)&wqh, g_Wqh);
    cudaGetSymbolAddress((void**)&wkh, g_Wkh);
    cudaGetSymbolAddress((void**)&wvh, g_Wvh);
    cudaGetSymbolAddress((void**)&woh, g_Woh);
    cudaGetSymbolAddress((void**)&qh, g_Qh);
    cudaGetSymbolAddress((void**)&kh, g_Kh2);
    cudaGetSymbolAddress((void**)&vh, g_Vh2);
    cudaGetSymbolAddress((void**)&ah, g_Ahi);

    cudaFuncSetAttribute(qkv_proj, cudaFuncAttributeMaxDynamicSharedMemorySize,
                         2 * 3 * TSZ);                     // 98304 (split-2)
    cudaFuncSetAttribute(o_proj, cudaFuncAttributeMaxDynamicSharedMemorySize,
                         2 * 2 * TSZ);                     // 65536
    cudaFuncSetAttribute(flash_hmma, cudaFuncAttributeMaxDynamicSharedMemorySize,
                         FA_SMEM);

    const float WS = 1024.0f;
    dim3 blk(256);

    // Splits
    split_f32<<<1024, 256>>>(x, xh, xl, (NTOK * KDIM) / 4, 1.0f);
    split_weights<<<1024, 256>>>(q_w, k_w, v_w, o_w, wqh, wkh, wvh, woh, WS);

    // Fused Q/K/V projections (all split-2)
    qkv_proj<<<dim3(48, 32), blk, 2 * 3 * TSZ>>>(xh, xl, wqh, wkh, wvh,
                                                 q_b, k_b, v_b, qh, kh, vh);

    // Attention
    flash_hmma<<<dim3(SEQL / 128, NHEAD, NBATCH), blk, FA_SMEM>>>(qh, kh, vh, ah);

    // Output projection (pure fp16)
    o_proj<<<dim3(32, 32), blk, 2 * 2 * TSZ>>>(ah, woh, o_b, out);
}

// round 14
// speedup vs baseline: 1.0938x; 1.0347x over previous
#include <cuda_runtime.h>
#include <cuda_fp16.h>
#include <cstdint>

#define HIDN  4096
#define NBATCH 2
#define SEQL  2048
#define NHEAD 32
#define NKVH  8
#define DHEAD 128
#define NTOK  (NBATCH * SEQL)
#define KDIM  4096

// ---------------------------------------------------------------------------
// Device scratch (allocation-free rule)
// ---------------------------------------------------------------------------
__device__ __half g_Xhi[(size_t)NTOK * KDIM];
__device__ __half g_Xlo[(size_t)NTOK * KDIM];
__device__ __half g_Wqh[(size_t)HIDN * KDIM];
__device__ __half g_Wkh[(size_t)NKVH * DHEAD * KDIM];
__device__ __half g_Wvh[(size_t)NKVH * DHEAD * KDIM];
__device__ __half g_Woh[(size_t)HIDN * KDIM];
// Q,K,V fp16 — [b, head, s, d]
__device__ __half g_Qh[(size_t)NBATCH * NHEAD * SEQL * DHEAD];
__device__ __half g_Kh2[(size_t)NBATCH * NKVH * SEQL * DHEAD];
__device__ __half g_Vh2[(size_t)NBATCH * NKVH * SEQL * DHEAD];
// attention output [t, hid], fp16 (o-proj input)
__device__ __half g_Ahi[(size_t)NTOK * KDIM];

// ---------------------------------------------------------------------------
// PTX helpers (sm_80-era, safe at compute_103)
// ---------------------------------------------------------------------------
__device__ __forceinline__ uint32_t smem_u32(const void* p) {
    uint32_t r;
    asm("{ .reg .u64 t; cvta.to.shared.u64 t, %1; cvt.u32.u64 %0, t; }"
        : "=r"(r) : "l"(p));
    return r;
}

#define CP16(dst, src) \
    asm volatile("cp.async.cg.shared.global [%0], [%1], 16;" \
                 :: "r"(dst), "l"(src) : "memory")
#define CP_COMMIT() asm volatile("cp.async.commit_group;" ::: "memory")
#define CP_WAIT(n)  asm volatile("cp.async.wait_group %0;" :: "n"(n) : "memory")

__device__ __forceinline__ void ldsm4(uint32_t& r0, uint32_t& r1,
                                      uint32_t& r2, uint32_t& r3, uint32_t a) {
    asm volatile("ldmatrix.sync.aligned.m8n8.x4.shared.b16 {%0,%1,%2,%3}, [%4];"
                 : "=r"(r0), "=r"(r1), "=r"(r2), "=r"(r3) : "r"(a));
}
__device__ __forceinline__ void ldsm4t(uint32_t& r0, uint32_t& r1,
                                       uint32_t& r2, uint32_t& r3, uint32_t a) {
    asm volatile("ldmatrix.sync.aligned.m8n8.x4.trans.shared.b16 {%0,%1,%2,%3}, [%4];"
                 : "=r"(r0), "=r"(r1), "=r"(r2), "=r"(r3) : "r"(a));
}

__device__ __forceinline__ void mma16816(float* c, const uint32_t* a,
                                         uint32_t b0, uint32_t b1) {
    asm volatile(
        "mma.sync.aligned.m16n8k16.row.col.f32.f16.f16.f32 "
        "{%0,%1,%2,%3}, {%4,%5,%6,%7}, {%8,%9}, {%0,%1,%2,%3};"
        : "+f"(c[0]), "+f"(c[1]), "+f"(c[2]), "+f"(c[3])
        : "r"(a[0]), "r"(a[1]), "r"(a[2]), "r"(a[3]), "r"(b0), "r"(b1));
}

// ---------------------------------------------------------------------------
// Fused split: x (hi/lo) + all four weights (hi) in ONE kernel.
// Total float4s = 4M + 4M + 1M + 1M + 4M = 14,680,064
//               = 2048 blocks * 256 threads * 28 iters EXACTLY.
// ---------------------------------------------------------------------------
#define XW4 ((NTOK * KDIM) / 4)               // 4,194,304
#define QW4 ((HIDN * KDIM) / 4)               // 4,194,304
#define KW4 ((NKVH * DHEAD * KDIM) / 4)       // 1,048,576
#define SPLIT_BLOCKS 2048
#define SPLIT_ITERS  28
// (XW4 + QW4 + 2*KW4 + QW4) == SPLIT_BLOCKS*256*SPLIT_ITERS  — exact.

__global__ void split_all(const float* __restrict__ x,
                          const float* __restrict__ q_w,
                          const float* __restrict__ k_w,
                          const float* __restrict__ v_w,
                          const float* __restrict__ o_w,
                          __half* __restrict__ xh, __half* __restrict__ xl,
                          __half* __restrict__ wqh, __half* __restrict__ wkh,
                          __half* __restrict__ wvh, __half* __restrict__ woh,
                          float ws)
{
    const int stride = SPLIT_BLOCKS * 256;
    const int base = blockIdx.x * 256 + threadIdx.x;
#pragma unroll 4
    for (int it = 0; it < SPLIT_ITERS; ++it) {
        int j = base + it * stride;
        const float* src;
        __half *hi, *lo = nullptr;
        float scale;
        if (j < XW4) { src = x; hi = xh; lo = xl; scale = 1.0f; }
        else if ((j -= XW4) < QW4) { src = q_w; hi = wqh; scale = ws; }
        else if ((j -= QW4) < KW4) { src = k_w; hi = wkh; scale = ws; }
        else if ((j -= KW4) < KW4) { src = v_w; hi = wvh; scale = ws; }
        else { j -= KW4; src = o_w; hi = woh; scale = ws; }

        float4 v = ((const float4*)src)[j];
        v.x *= scale; v.y *= scale; v.z *= scale; v.w *= scale;
        __half hx = __float2half_rn(v.x), hy = __float2half_rn(v.y);
        __half hz = __float2half_rn(v.z), hw = __float2half_rn(v.w);
        __half2 h01 = __halves2half2(hx, hy), h23 = __halves2half2(hz, hw);
        uint2 hp;
        hp.x = *(uint32_t*)&h01; hp.y = *(uint32_t*)&h23;
        ((uint2*)hi)[j] = hp;
        if (lo) {
            __half lx = __float2half_rn(v.x - __half2float(hx));
            __half ly = __float2half_rn(v.y - __half2float(hy));
            __half lz = __float2half_rn(v.z - __half2float(hz));
            __half lw = __float2half_rn(v.w - __half2float(hw));
            __half2 l01 = __halves2half2(lx, ly), l23 = __halves2half2(lz, lw);
            uint2 lp;
            lp.x = *(uint32_t*)&l01; lp.y = *(uint32_t*)&l23;
            ((uint2*)lo)[j] = lp;
        }
    }
}

// ---------------------------------------------------------------------------
// HMMA NT GEMM body (unchanged from R12)
// ---------------------------------------------------------------------------
#define TSZ   16384
#define IWS_C (1.0f / 1024.0f)

template <int SPLIT>
__device__ __forceinline__
void gemm_body(int bx, int by,
               const __half* __restrict__ Ahi, const __half* __restrict__ Alo,
               const __half* __restrict__ Bhi,
               const float* __restrict__ bias, float* __restrict__ C,
               __half* __restrict__ Chi,
               int N, int mode, int nheads, float outscale)
{
    extern __shared__ __align__(1024) char sm[];
    constexpr int NT   = SPLIT + 1;
    constexpr int BOFF = (SPLIT >= 2) ? 2 : 1;
    const int tid  = threadIdx.x;
    const int wid  = tid >> 5;
    const int lane = tid & 31;
    const int m0 = by * 128;
    const int n0 = bx * 128;
    const int wm = (wid >> 2) * 64;
    const int wn = (wid & 3) * 32;
    const uint32_t sbase = smem_u32(sm);

    const __half* Ah = Ahi + (size_t)m0 * KDIM;
    const __half* Al = (SPLIT >= 2) ? (Alo + (size_t)m0 * KDIM) : nullptr;
    const __half* Bh = Bhi + (size_t)n0 * KDIM;

    float acc[4][4][4];
#pragma unroll
    for (int i = 0; i < 4; i++)
#pragma unroll
        for (int j = 0; j < 4; j++)
#pragma unroll
            for (int k = 0; k < 4; k++) acc[i][j][k] = 0.0f;

    auto load_stage = [&](int s, int k0) {
        const uint32_t base = sbase + s * NT * TSZ;
#pragma unroll
        for (int i = 0; i < 4; i++) {
            const int idx = tid + i * 256;
            const int r = idx >> 3, c = idx & 7;
            const uint32_t dst = r * 128 + (((uint32_t)(c ^ (r & 7))) << 4);
            const size_t src = (size_t)r * KDIM + k0 + c * 8;
            CP16(base + dst, (const char*)(Ah + src));
            if (SPLIT >= 2)
                CP16(base + TSZ + dst, (const char*)(Al + src));
            CP16(base + BOFF * TSZ + dst, (const char*)(Bh + src));
        }
        CP_COMMIT();
    };

    load_stage(0, 0);

    const int NIT = KDIM / 64;
    for (int it = 0; it < NIT; ++it) {
        if (it + 1 < NIT) load_stage((it + 1) & 1, (it + 1) * 64);
        if (it + 1 < NIT) { CP_WAIT(1); } else { CP_WAIT(0); }
        __syncthreads();

        const uint32_t stg = sbase + (it & 1) * NT * TSZ;
        const uint32_t sAh = stg, sAl = stg + TSZ;
        const uint32_t sBh = stg + BOFF * TSZ;

        uint32_t bh[4][4];
#pragma unroll
        for (int k16 = 0; k16 < 4; ++k16) {
            if ((k16 & 1) == 0) {
#pragma unroll
                for (int nt = 0; nt < 4; ++nt) {
                    const int r = wn + nt * 8 + (lane & 7);
                    const int c = k16 * 2 + (lane >> 3);
                    const uint32_t off = r * 128 + (((uint32_t)(c ^ (r & 7))) << 4);
                    ldsm4(bh[nt][0], bh[nt][1], bh[nt][2], bh[nt][3], sBh + off);
                }
            }
            const int bo = (k16 & 1) * 2;

            uint32_t ah[4][4], al[4][4];
#pragma unroll
            for (int mt = 0; mt < 4; ++mt) {
                const int r = wm + mt * 16 + (lane & 15);
                const int c = k16 * 2 + (lane >> 4);
                const uint32_t off = r * 128 + (((uint32_t)(c ^ (r & 7))) << 4);
                ldsm4(ah[mt][0], ah[mt][1], ah[mt][2], ah[mt][3], sAh + off);
                if (SPLIT >= 2)
                    ldsm4(al[mt][0], al[mt][1], al[mt][2], al[mt][3], sAl + off);
            }
#pragma unroll
            for (int mt = 0; mt < 4; ++mt)
#pragma unroll
                for (int nt = 0; nt < 4; ++nt) {
                    mma16816(acc[mt][nt], ah[mt], bh[nt][bo], bh[nt][bo + 1]);
                    if (SPLIT >= 2)
                        mma16816(acc[mt][nt], al[mt], bh[nt][bo], bh[nt][bo + 1]);
                }
        }
        __syncthreads();
    }

#pragma unroll
    for (int mt = 0; mt < 4; ++mt) {
#pragma unroll
        for (int nt = 0; nt < 4; ++nt) {
            const int o = n0 + wn + nt * 8 + 2 * (lane & 3);
            const float b0 = bias[o], b1 = bias[o + 1];
#pragma unroll
            for (int half = 0; half < 2; ++half) {
                const int t = m0 + wm + mt * 16 + (lane >> 2) + half * 8;
                float vx = acc[mt][nt][half * 2 + 0] * outscale + b0;
                float vy = acc[mt][nt][half * 2 + 1] * outscale + b1;
                if (mode == 0) {
                    const int bb = t >> 11, s = t & 2047;
                    const int hh = o >> 7, d = o & 127;
                    const size_t idx =
                        (((size_t)(bb * nheads + hh)) * SEQL + s) * DHEAD + d;
                    *(__half2*)&Chi[idx] = __floats2half2_rn(vx, vy);
                } else {
                    float2 v; v.x = vx; v.y = vy;
                    *(float2*)&C[(size_t)t * N + o] = v;
                }
            }
        }
    }
}

__global__ __launch_bounds__(256, 1)
void qkv_proj(const __half* __restrict__ xh, const __half* __restrict__ xl,
              const __half* __restrict__ wqh, const __half* __restrict__ wkh,
              const __half* __restrict__ wvh,
              const float* __restrict__ q_b, const float* __restrict__ k_b,
              const float* __restrict__ v_b,
              __half* __restrict__ qh, __half* __restrict__ kh,
              __half* __restrict__ vh)
{
    const int bx = blockIdx.x;
    if (bx < 32) {
        gemm_body<2>(bx, blockIdx.y, xh, xl, wqh, q_b, nullptr,
                     qh, HIDN, 0, NHEAD, IWS_C);
    } else if (bx < 40) {
        gemm_body<2>(bx - 32, blockIdx.y, xh, xl, wkh, k_b, nullptr,
                     kh, NKVH * DHEAD, 0, NKVH, IWS_C);
    } else {
        gemm_body<2>(bx - 40, blockIdx.y, xh, xl, wvh, v_b, nullptr,
                     vh, NKVH * DHEAD, 0, NKVH, IWS_C);
    }
}

// o_proj: SPLIT=1 body fits 128 regs -> allow 2 CTAs/SM (smem 64KB each).
__global__ __launch_bounds__(256, 2)
void o_proj(const __half* __restrict__ ah,
            const __half* __restrict__ woh, const float* __restrict__ o_b,
            float* __restrict__ out)
{
    gemm_body<1>(blockIdx.x, blockIdx.y, ah, nullptr, woh, o_b, out,
                 nullptr, HIDN, 1, 0, IWS_C);
}

// ---------------------------------------------------------------------------
// HMMA causal flash attention (unchanged from R12).
// ---------------------------------------------------------------------------
#define FA_QT    32768
#define FA_KVT   16384
#define FA_STG   (2 * FA_KVT)               // 32768
#define FA_SMEM  (FA_QT + 2 * FA_STG)       // 98304

__global__ __launch_bounds__(256, 1)
void flash_hmma(const __half* __restrict__ Qh_,
                const __half* __restrict__ Kh_,
                const __half* __restrict__ Vh_,
                __half* __restrict__ Ohi)
{
    extern __shared__ __align__(1024) char sm[];
    const uint32_t sb  = smem_u32(sm);
    const uint32_t sQh = sb;
    const uint32_t sKV = sb + FA_QT;

    const int tid = threadIdx.x, wid = tid >> 5, lane = tid & 31;
    const int qb = gridDim.x - 1 - blockIdx.x;
    const int q0 = qb * 128;
    const int h = blockIdx.y, b = blockIdx.z, kvh = h & 7;
    const int wq = wid * 16;
    const float scale = 0.08838834764831845f;

    const size_t qbase  = (((size_t)(b * NHEAD + h))  * SEQL + q0) * DHEAD;
    const size_t kvbase = (((size_t)(b * NKVH + kvh)) * SEQL) * DHEAD;

#pragma unroll
    for (int i = 0; i < 8; i++) {
        const int idx = tid + i * 256;
        const int r = idx >> 4, c = idx & 15;
        const uint32_t dst = r * 256 + (((uint32_t)(c ^ (r & 7))) << 4);
        CP16(sQh + dst, (const char*)(Qh_ + qbase + (size_t)r * DHEAD + c * 8));
    }
    auto load_kv = [&](int j, int s) {
        const uint32_t st = sKV + s * FA_STG;
        const size_t base = kvbase + (size_t)j * 64 * DHEAD;
#pragma unroll
        for (int i = 0; i < 4; i++) {
            const int idx = tid + i * 256;
            const int r = idx >> 4, c = idx & 15;
            const uint32_t dst = r * 256 + (((uint32_t)(c ^ (r & 7))) << 4);
            const size_t src = base + (size_t)r * DHEAD + c * 8;
            CP16(st + dst,          (const char*)(Kh_ + src));
            CP16(st + FA_KVT + dst, (const char*)(Vh_ + src));
        }
    };
    load_kv(0, 0);
    CP_COMMIT();

    float O[16][4];
#pragma unroll
    for (int i = 0; i < 16; i++)
#pragma unroll
        for (int k = 0; k < 4; k++) O[i][k] = 0.0f;
    float m0 = -1e30f, m1 = -1e30f, l0 = 0.0f, l1 = 0.0f;

    const int njt = (q0 + 128) / 64;
    for (int j = 0; j < njt; j++) {
        if (j + 1 < njt) { load_kv(j + 1, (j + 1) & 1); CP_COMMIT(); CP_WAIT(1); }
        else             { CP_WAIT(0); }
        __syncthreads();
        const uint32_t st = sKV + (j & 1) * FA_STG;
        const int j0 = j * 64;

        if (q0 + wq + 15 >= j0) {
            float S[8][4];
#pragma unroll
            for (int nt = 0; nt < 8; nt++)
#pragma unroll
                for (int k = 0; k < 4; k++) S[nt][k] = 0.0f;

#pragma unroll
            for (int kp = 0; kp < 4; kp++) {
                uint32_t ah[2][4];
#pragma unroll
                for (int x = 0; x < 2; x++) {
                    const int ks = kp * 2 + x;
                    const int r = wq + (lane & 15);
                    const int c = ks * 2 + (lane >> 4);
                    const uint32_t off = r * 256 + (((uint32_t)(c ^ (r & 7))) << 4);
                    ldsm4(ah[x][0], ah[x][1], ah[x][2], ah[x][3], sQh + off);
                }
#pragma unroll
                for (int nt = 0; nt < 8; nt++) {
                    const int r = nt * 8 + (lane & 7);
                    const int c = kp * 4 + (lane >> 3);
                    const uint32_t off = r * 256 + (((uint32_t)(c ^ (r & 7))) << 4);
                    uint32_t kh[4];
                    ldsm4(kh[0], kh[1], kh[2], kh[3], st + off);
                    mma16816(S[nt], ah[0], kh[0], kh[1]);
                    mma16816(S[nt], ah[1], kh[2], kh[3]);
                }
            }

            if (j0 + 63 > q0 + wq) {
                const int row0 = q0 + wq + (lane >> 2), row1 = row0 + 8;
#pragma unroll
                for (int nt = 0; nt < 8; nt++) {
                    const int cb = j0 + nt * 8 + 2 * (lane & 3);
                    if (cb     > row0) S[nt][0] = -1e30f;
                    if (cb + 1 > row0) S[nt][1] = -1e30f;
                    if (cb     > row1) S[nt][2] = -1e30f;
                    if (cb + 1 > row1) S[nt][3] = -1e30f;
                }
            }

            float tm0 = -1e30f, tm1 = -1e30f;
#pragma unroll
            for (int nt = 0; nt < 8; nt++) {
                tm0 = fmaxf(tm0, fmaxf(S[nt][0], S[nt][1]));
                tm1 = fmaxf(tm1, fmaxf(S[nt][2], S[nt][3]));
            }
            tm0 = fmaxf(tm0, __shfl_xor_sync(0xffffffffu, tm0, 1));
            tm0 = fmaxf(tm0, __shfl_xor_sync(0xffffffffu, tm0, 2));
            tm1 = fmaxf(tm1, __shfl_xor_sync(0xffffffffu, tm1, 1));
            tm1 = fmaxf(tm1, __shfl_xor_sync(0xffffffffu, tm1, 2));
            const float mn0 = fmaxf(m0, tm0), mn1 = fmaxf(m1, tm1);
            const float cr0 = __expf((m0 - mn0) * scale);
            const float cr1 = __expf((m1 - mn1) * scale);
            m0 = mn0; m1 = mn1;

            uint32_t ph[8][2];
            float ps0 = 0.0f, ps1 = 0.0f;
#pragma unroll
            for (int nt = 0; nt < 8; nt++) {
                const float p0 = __expf((S[nt][0] - mn0) * scale);
                const float p1 = __expf((S[nt][1] - mn0) * scale);
                const float p2 = __expf((S[nt][2] - mn1) * scale);
                const float p3 = __expf((S[nt][3] - mn1) * scale);
                const __half h0 = __float2half_rn(p0), h1 = __float2half_rn(p1);
                const __half h2 = __float2half_rn(p2), h3 = __float2half_rn(p3);
                // l accumulates the ROUNDED p (numerator/denominator consistent)
                ps0 += __half2float(h0) + __half2float(h1);
                ps1 += __half2float(h2) + __half2float(h3);
                __half2 a01 = __halves2half2(h0, h1), a23 = __halves2half2(h2, h3);
                ph[nt][0] = *(uint32_t*)&a01;  ph[nt][1] = *(uint32_t*)&a23;
            }
            ps0 += __shfl_xor_sync(0xffffffffu, ps0, 1);
            ps0 += __shfl_xor_sync(0xffffffffu, ps0, 2);
            ps1 += __shfl_xor_sync(0xffffffffu, ps1, 1);
            ps1 += __shfl_xor_sync(0xffffffffu, ps1, 2);
            l0 = l0 * cr0 + ps0;
            l1 = l1 * cr1 + ps1;
#pragma unroll
            for (int nt = 0; nt < 16; nt++) {
                O[nt][0] *= cr0; O[nt][1] *= cr0;
                O[nt][2] *= cr1; O[nt][3] *= cr1;
            }

            // ---- PV: O += round(P) . V ----
#pragma unroll
            for (int kt = 0; kt < 4; kt++) {
                uint32_t pah[4];
                pah[0] = ph[2 * kt][0];     pah[1] = ph[2 * kt][1];
                pah[2] = ph[2 * kt + 1][0]; pah[3] = ph[2 * kt + 1][1];
#pragma unroll
                for (int np = 0; np < 8; np++) {
                    const int r = kt * 16 + (lane & 15);
                    const int c = np * 2 + (lane >> 4);
                    const uint32_t off = r * 256 + (((uint32_t)(c ^ (r & 7))) << 4);
                    uint32_t vh[4];
                    ldsm4t(vh[0], vh[1], vh[2], vh[3], st + FA_KVT + off);
                    mma16816(O[2 * np],     pah, vh[0], vh[1]);
                    mma16816(O[2 * np + 1], pah, vh[2], vh[3]);
                }
            }
        }
        __syncthreads();
    }

    const float i0 = 1.0f / l0, i1 = 1.0f / l1;
    const int t0 = b * SEQL + q0 + wq + (lane >> 2);
#pragma unroll
    for (int nt = 0; nt < 16; nt++) {
        const int col = h * DHEAD + nt * 8 + 2 * (lane & 3);
        *(__half2*)&Ohi[(size_t)t0 * KDIM + col] =
            __floats2half2_rn(O[nt][0] * i0, O[nt][1] * i0);
        *(__half2*)&Ohi[(size_t)(t0 + 8) * KDIM + col] =
            __floats2half2_rn(O[nt][2] * i1, O[nt][3] * i1);
    }
}

// ---------------------------------------------------------------------------
extern "C" void kernel_launch(void* const* d_in, const int* in_sizes, int n_in,
                              void* d_out, int out_size)
{
    const float* x   = (const float*)d_in[0];
    // d_in[1] = mask: causal structure applied analytically, not read.
    const float* q_w = (const float*)d_in[2];
    const float* q_b = (const float*)d_in[3];
    const float* k_w = (const float*)d_in[4];
    const float* k_b = (const float*)d_in[5];
    const float* v_w = (const float*)d_in[6];
    const float* v_b = (const float*)d_in[7];
    const float* o_w = (const float*)d_in[8];
    const float* o_b = (const float*)d_in[9];
    float* out = (float*)d_out;

    __half *xh, *xl, *wqh, *wkh, *wvh, *woh;
    __half *qh, *kh, *vh, *ah;
    cudaGetSymbolAddress((void**)&xh, g_Xhi);   cudaGetSymbolAddress((void**)&xl, g_Xlo);
    cudaGetSymbolAddress((void**)&wqh, g_Wqh);
    cudaGetSymbolAddress((void**)&wkh, g_Wkh);
    cudaGetSymbolAddress((void**)&wvh, g_Wvh);
    cudaGetSymbolAddress((void**)&woh, g_Woh);
    cudaGetSymbolAddress((void**)&qh, g_Qh);
    cudaGetSymbolAddress((void**)&kh, g_Kh2);
    cudaGetSymbolAddress((void**)&vh, g_Vh2);
    cudaGetSymbolAddress((void**)&ah, g_Ahi);

    cudaFuncSetAttribute(qkv_proj, cudaFuncAttributeMaxDynamicSharedMemorySize,
                         2 * 3 * TSZ);                     // 98304 (split-2)
    cudaFuncSetAttribute(o_proj, cudaFuncAttributeMaxDynamicSharedMemorySize,
                         2 * 2 * TSZ);                     // 65536
    cudaFuncSetAttribute(flash_hmma, cudaFuncAttributeMaxDynamicSharedMemorySize,
                         FA_SMEM);

    const float WS = 1024.0f;
    dim3 blk(256);

    // Fused splits: x hi/lo + all weights hi, one launch
    split_all<<<SPLIT_BLOCKS, 256>>>(x, q_w, k_w, v_w, o_w,
                                     xh, xl, wqh, wkh, wvh, woh, WS);

    // Fused Q/K/V projections (all split-2)
    qkv_proj<<<dim3(48, 32), blk, 2 * 3 * TSZ>>>(xh, xl, wqh, wkh, wvh,
                                                 q_b, k_b, v_b, qh, kh, vh);

    // Attention
    flash_hmma<<<dim3(SEQL / 128, NHEAD, NBATCH), blk, FA_SMEM>>>(qh, kh, vh, ah);

    // Output projection (pure fp16, 2 CTAs/SM)
    o_proj<<<dim3(32, 32), blk, 2 * 2 * TSZ>>>(ah, woh, o_b, out);
}

// round 15
// speedup vs baseline: 1.1319x; 1.0349x over previous
#include <cuda_runtime.h>
#include <cuda_fp16.h>
#include <cstdint>

#define HIDN  4096
#define NBATCH 2
#define SEQL  2048
#define NHEAD 32
#define NKVH  8
#define DHEAD 128
#define NTOK  (NBATCH * SEQL)
#define KDIM  4096

// ---------------------------------------------------------------------------
// Device scratch (allocation-free rule)
// ---------------------------------------------------------------------------
__device__ __half g_Xhi[(size_t)NTOK * KDIM];
__device__ __half g_Xlo[(size_t)NTOK * KDIM];
__device__ __half g_Wqh[(size_t)HIDN * KDIM];
__device__ __half g_Wkh[(size_t)NKVH * DHEAD * KDIM];
__device__ __half g_Wvh[(size_t)NKVH * DHEAD * KDIM];
__device__ __half g_Woh[(size_t)HIDN * KDIM];
// Q,K,V fp16 — [b, head, s, d]
__device__ __half g_Qh[(size_t)NBATCH * NHEAD * SEQL * DHEAD];
__device__ __half g_Kh2[(size_t)NBATCH * NKVH * SEQL * DHEAD];
__device__ __half g_Vh2[(size_t)NBATCH * NKVH * SEQL * DHEAD];
// attention output [t, hid], fp16 (o-proj input)
__device__ __half g_Ahi[(size_t)NTOK * KDIM];

// ---------------------------------------------------------------------------
// PTX helpers (sm_80-era, safe at compute_103)
// ---------------------------------------------------------------------------
__device__ __forceinline__ uint32_t smem_u32(const void* p) {
    uint32_t r;
    asm("{ .reg .u64 t; cvta.to.shared.u64 t, %1; cvt.u32.u64 %0, t; }"
        : "=r"(r) : "l"(p));
    return r;
}

#define CP16(dst, src) \
    asm volatile("cp.async.cg.shared.global [%0], [%1], 16;" \
                 :: "r"(dst), "l"(src) : "memory")
#define CP_COMMIT() asm volatile("cp.async.commit_group;" ::: "memory")
#define CP_WAIT(n)  asm volatile("cp.async.wait_group %0;" :: "n"(n) : "memory")

__device__ __forceinline__ void ldsm4(uint32_t& r0, uint32_t& r1,
                                      uint32_t& r2, uint32_t& r3, uint32_t a) {
    asm volatile("ldmatrix.sync.aligned.m8n8.x4.shared.b16 {%0,%1,%2,%3}, [%4];"
                 : "=r"(r0), "=r"(r1), "=r"(r2), "=r"(r3) : "r"(a));
}
__device__ __forceinline__ void ldsm4t(uint32_t& r0, uint32_t& r1,
                                       uint32_t& r2, uint32_t& r3, uint32_t a) {
    asm volatile("ldmatrix.sync.aligned.m8n8.x4.trans.shared.b16 {%0,%1,%2,%3}, [%4];"
                 : "=r"(r0), "=r"(r1), "=r"(r2), "=r"(r3) : "r"(a));
}

__device__ __forceinline__ void mma16816(float* c, const uint32_t* a,
                                         uint32_t b0, uint32_t b1) {
    asm volatile(
        "mma.sync.aligned.m16n8k16.row.col.f32.f16.f16.f32 "
        "{%0,%1,%2,%3}, {%4,%5,%6,%7}, {%8,%9}, {%0,%1,%2,%3};"
        : "+f"(c[0]), "+f"(c[1]), "+f"(c[2]), "+f"(c[3])
        : "r"(a[0]), "r"(a[1]), "r"(a[2]), "r"(a[3]), "r"(b0), "r"(b1));
}

// ---------------------------------------------------------------------------
// Fused split: x (hi/lo) + all four weights (hi) in ONE kernel.
// Total float4s = 14,680,064 = 2048 blocks * 256 threads * 28 iters EXACTLY.
// ---------------------------------------------------------------------------
#define XW4 ((NTOK * KDIM) / 4)
#define QW4 ((HIDN * KDIM) / 4)
#define KW4 ((NKVH * DHEAD * KDIM) / 4)
#define SPLIT_BLOCKS 2048
#define SPLIT_ITERS  28

__global__ void split_all(const float* __restrict__ x,
                          const float* __restrict__ q_w,
                          const float* __restrict__ k_w,
                          const float* __restrict__ v_w,
                          const float* __restrict__ o_w,
                          __half* __restrict__ xh, __half* __restrict__ xl,
                          __half* __restrict__ wqh, __half* __restrict__ wkh,
                          __half* __restrict__ wvh, __half* __restrict__ woh,
                          float ws)
{
    const int stride = SPLIT_BLOCKS * 256;
    const int base = blockIdx.x * 256 + threadIdx.x;
#pragma unroll 4
    for (int it = 0; it < SPLIT_ITERS; ++it) {
        int j = base + it * stride;
        const float* src;
        __half *hi, *lo = nullptr;
        float scale;
        if (j < XW4) { src = x; hi = xh; lo = xl; scale = 1.0f; }
        else if ((j -= XW4) < QW4) { src = q_w; hi = wqh; scale = ws; }
        else if ((j -= QW4) < KW4) { src = k_w; hi = wkh; scale = ws; }
        else if ((j -= KW4) < KW4) { src = v_w; hi = wvh; scale = ws; }
        else { j -= KW4; src = o_w; hi = woh; scale = ws; }

        float4 v = ((const float4*)src)[j];
        v.x *= scale; v.y *= scale; v.z *= scale; v.w *= scale;
        __half hx = __float2half_rn(v.x), hy = __float2half_rn(v.y);
        __half hz = __float2half_rn(v.z), hw = __float2half_rn(v.w);
        __half2 h01 = __halves2half2(hx, hy), h23 = __halves2half2(hz, hw);
        uint2 hp;
        hp.x = *(uint32_t*)&h01; hp.y = *(uint32_t*)&h23;
        ((uint2*)hi)[j] = hp;
        if (lo) {
            __half lx = __float2half_rn(v.x - __half2float(hx));
            __half ly = __float2half_rn(v.y - __half2float(hy));
            __half lz = __float2half_rn(v.z - __half2float(hz));
            __half lw = __float2half_rn(v.w - __half2float(hw));
            __half2 l01 = __halves2half2(lx, ly), l23 = __halves2half2(lz, lw);
            uint2 lp;
            lp.x = *(uint32_t*)&l01; lp.y = *(uint32_t*)&l23;
            ((uint2*)lo)[j] = lp;
        }
    }
}

// ---------------------------------------------------------------------------
// HMMA NT GEMM body, templated on SPLIT and K-chunk KC.
// tiling: CTA 128x128, warp 64x32, 2-stage cp.async.
// SPLIT=1: AhWh;  SPLIT=2: AhWh + AlWh
// mode 0: fp16 into [b, head, s, d]; mode 1: fp32 row-major
// ---------------------------------------------------------------------------
#define IWS_C (1.0f / 1024.0f)

template <int SPLIT, int KC>
__device__ __forceinline__
void gemm_body(int bx, int by,
               const __half* __restrict__ Ahi, const __half* __restrict__ Alo,
               const __half* __restrict__ Bhi,
               const float* __restrict__ bias, float* __restrict__ C,
               __half* __restrict__ Chi,
               int N, int mode, int nheads, float outscale)
{
    extern __shared__ __align__(1024) char sm[];
    constexpr int ROWB = KC * 2;              // row bytes
    constexpr int TSZK = 128 * ROWB;          // one 128 x KC fp16 tile
    constexpr int CPR  = KC / 8;              // 16B chunks per row (<=16)
    constexpr int NT   = SPLIT + 1;
    constexpr int BOFF = (SPLIT >= 2) ? 2 : 1;
    const int tid  = threadIdx.x;
    const int wid  = tid >> 5;
    const int lane = tid & 31;
    const int m0 = by * 128;
    const int n0 = bx * 128;
    const int wm = (wid >> 2) * 64;
    const int wn = (wid & 3) * 32;
    const uint32_t sbase = smem_u32(sm);

    const __half* Ah = Ahi + (size_t)m0 * KDIM;
    const __half* Al = (SPLIT >= 2) ? (Alo + (size_t)m0 * KDIM) : nullptr;
    const __half* Bh = Bhi + (size_t)n0 * KDIM;

    float acc[4][4][4];
#pragma unroll
    for (int i = 0; i < 4; i++)
#pragma unroll
        for (int j = 0; j < 4; j++)
#pragma unroll
            for (int k = 0; k < 4; k++) acc[i][j][k] = 0.0f;

    auto load_stage = [&](int s, int k0) {
        const uint32_t base = sbase + s * NT * TSZK;
#pragma unroll
        for (int i = 0; i < (128 * CPR) / 256; i++) {
            const int idx = tid + i * 256;
            const int r = idx / CPR, c = idx % CPR;
            const uint32_t dst = r * ROWB + (((uint32_t)(c ^ (r & 7))) << 4);
            const size_t src = (size_t)r * KDIM + k0 + c * 8;
            CP16(base + dst, (const char*)(Ah + src));
            if (SPLIT >= 2)
                CP16(base + TSZK + dst, (const char*)(Al + src));
            CP16(base + BOFF * TSZK + dst, (const char*)(Bh + src));
        }
        CP_COMMIT();
    };

    load_stage(0, 0);

    const int NIT = KDIM / KC;
    for (int it = 0; it < NIT; ++it) {
        if (it + 1 < NIT) load_stage((it + 1) & 1, (it + 1) * KC);
        if (it + 1 < NIT) { CP_WAIT(1); } else { CP_WAIT(0); }
        __syncthreads();

        const uint32_t stg = sbase + (it & 1) * NT * TSZK;
        const uint32_t sAh = stg, sAl = stg + TSZK;
        const uint32_t sBh = stg + BOFF * TSZK;

        uint32_t bh[4][4];
#pragma unroll
        for (int k16 = 0; k16 < KC / 16; ++k16) {
            if ((k16 & 1) == 0) {
#pragma unroll
                for (int nt = 0; nt < 4; ++nt) {
                    const int r = wn + nt * 8 + (lane & 7);
                    const int c = k16 * 2 + (lane >> 3);
                    const uint32_t off = r * ROWB + (((uint32_t)(c ^ (r & 7))) << 4);
                    ldsm4(bh[nt][0], bh[nt][1], bh[nt][2], bh[nt][3], sBh + off);
                }
            }
            const int bo = (k16 & 1) * 2;

            uint32_t ah[4][4], al[4][4];
#pragma unroll
            for (int mt = 0; mt < 4; ++mt) {
                const int r = wm + mt * 16 + (lane & 15);
                const int c = k16 * 2 + (lane >> 4);
                const uint32_t off = r * ROWB + (((uint32_t)(c ^ (r & 7))) << 4);
                ldsm4(ah[mt][0], ah[mt][1], ah[mt][2], ah[mt][3], sAh + off);
                if (SPLIT >= 2)
                    ldsm4(al[mt][0], al[mt][1], al[mt][2], al[mt][3], sAl + off);
            }
#pragma unroll
            for (int mt = 0; mt < 4; ++mt)
#pragma unroll
                for (int nt = 0; nt < 4; ++nt) {
                    mma16816(acc[mt][nt], ah[mt], bh[nt][bo], bh[nt][bo + 1]);
                    if (SPLIT >= 2)
                        mma16816(acc[mt][nt], al[mt], bh[nt][bo], bh[nt][bo + 1]);
                }
        }
        __syncthreads();
    }

#pragma unroll
    for (int mt = 0; mt < 4; ++mt) {
#pragma unroll
        for (int nt = 0; nt < 4; ++nt) {
            const int o = n0 + wn + nt * 8 + 2 * (lane & 3);
            const float b0 = bias[o], b1 = bias[o + 1];
#pragma unroll
            for (int half = 0; half < 2; ++half) {
                const int t = m0 + wm + mt * 16 + (lane >> 2) + half * 8;
                float vx = acc[mt][nt][half * 2 + 0] * outscale + b0;
                float vy = acc[mt][nt][half * 2 + 1] * outscale + b1;
                if (mode == 0) {
                    const int bb = t >> 11, s = t & 2047;
                    const int hh = o >> 7, d = o & 127;
                    const size_t idx =
                        (((size_t)(bb * nheads + hh)) * SEQL + s) * DHEAD + d;
                    *(__half2*)&Chi[idx] = __floats2half2_rn(vx, vy);
                } else {
                    float2 v; v.x = vx; v.y = vy;
                    *(float2*)&C[(size_t)t * N + o] = v;
                }
            }
        }
    }
}

// Fused QKV projection, KC=128 (32 iterations, half the barriers).
// smem: 2 stages * 3 tiles * 32KB = 196608.
#define QKV_SMEM (2 * 3 * 128 * 256)
__global__ __launch_bounds__(256, 1)
void qkv_proj(const __half* __restrict__ xh, const __half* __restrict__ xl,
              const __half* __restrict__ wqh, const __half* __restrict__ wkh,
              const __half* __restrict__ wvh,
              const float* __restrict__ q_b, const float* __restrict__ k_b,
              const float* __restrict__ v_b,
              __half* __restrict__ qh, __half* __restrict__ kh,
              __half* __restrict__ vh)
{
    const int bx = blockIdx.x;
    if (bx < 32) {
        gemm_body<2, 128>(bx, blockIdx.y, xh, xl, wqh, q_b, nullptr,
                          qh, HIDN, 0, NHEAD, IWS_C);
    } else if (bx < 40) {
        gemm_body<2, 128>(bx - 32, blockIdx.y, xh, xl, wkh, k_b, nullptr,
                          kh, NKVH * DHEAD, 0, NKVH, IWS_C);
    } else {
        gemm_body<2, 128>(bx - 40, blockIdx.y, xh, xl, wvh, v_b, nullptr,
                          vh, NKVH * DHEAD, 0, NKVH, IWS_C);
    }
}

// o_proj: SPLIT=1, KC=64, 2 CTAs/SM (validated at tensor=70%).
#define OPJ_SMEM (2 * 2 * 128 * 128)
__global__ __launch_bounds__(256, 2)
void o_proj(const __half* __restrict__ ah,
            const __half* __restrict__ woh, const float* __restrict__ o_b,
            float* __restrict__ out)
{
    gemm_body<1, 64>(blockIdx.x, blockIdx.y, ah, nullptr, woh, o_b, out,
                     nullptr, HIDN, 1, 0, IWS_C);
}

// ---------------------------------------------------------------------------
// HMMA causal flash attention (unchanged from R12).
// ---------------------------------------------------------------------------
#define FA_QT    32768
#define FA_KVT   16384
#define FA_STG   (2 * FA_KVT)
#define FA_SMEM  (FA_QT + 2 * FA_STG)       // 98304

__global__ __launch_bounds__(256, 1)
void flash_hmma(const __half* __restrict__ Qh_,
                const __half* __restrict__ Kh_,
                const __half* __restrict__ Vh_,
                __half* __restrict__ Ohi)
{
    extern __shared__ __align__(1024) char sm[];
    const uint32_t sb  = smem_u32(sm);
    const uint32_t sQh = sb;
    const uint32_t sKV = sb + FA_QT;

    const int tid = threadIdx.x, wid = tid >> 5, lane = tid & 31;
    const int qb = gridDim.x - 1 - blockIdx.x;
    const int q0 = qb * 128;
    const int h = blockIdx.y, b = blockIdx.z, kvh = h & 7;
    const int wq = wid * 16;
    const float scale = 0.08838834764831845f;

    const size_t qbase  = (((size_t)(b * NHEAD + h))  * SEQL + q0) * DHEAD;
    const size_t kvbase = (((size_t)(b * NKVH + kvh)) * SEQL) * DHEAD;

#pragma unroll
    for (int i = 0; i < 8; i++) {
        const int idx = tid + i * 256;
        const int r = idx >> 4, c = idx & 15;
        const uint32_t dst = r * 256 + (((uint32_t)(c ^ (r & 7))) << 4);
        CP16(sQh + dst, (const char*)(Qh_ + qbase + (size_t)r * DHEAD + c * 8));
    }
    auto load_kv = [&](int j, int s) {
        const uint32_t st = sKV + s * FA_STG;
        const size_t base = kvbase + (size_t)j * 64 * DHEAD;
#pragma unroll
        for (int i = 0; i < 4; i++) {
            const int idx = tid + i * 256;
            const int r = idx >> 4, c = idx & 15;
            const uint32_t dst = r * 256 + (((uint32_t)(c ^ (r & 7))) << 4);
            const size_t src = base + (size_t)r * DHEAD + c * 8;
            CP16(st + dst,          (const char*)(Kh_ + src));
            CP16(st + FA_KVT + dst, (const char*)(Vh_ + src));
        }
    };
    load_kv(0, 0);
    CP_COMMIT();

    float O[16][4];
#pragma unroll
    for (int i = 0; i < 16; i++)
#pragma unroll
        for (int k = 0; k < 4; k++) O[i][k] = 0.0f;
    float m0 = -1e30f, m1 = -1e30f, l0 = 0.0f, l1 = 0.0f;

    const int njt = (q0 + 128) / 64;
    for (int j = 0; j < njt; j++) {
        if (j + 1 < njt) { load_kv(j + 1, (j + 1) & 1); CP_COMMIT(); CP_WAIT(1); }
        else             { CP_WAIT(0); }
        __syncthreads();
        const uint32_t st = sKV + (j & 1) * FA_STG;
        const int j0 = j * 64;

        if (q0 + wq + 15 >= j0) {
            float S[8][4];
#pragma unroll
            for (int nt = 0; nt < 8; nt++)
#pragma unroll
                for (int k = 0; k < 4; k++) S[nt][k] = 0.0f;

#pragma unroll
            for (int kp = 0; kp < 4; kp++) {
                uint32_t ah[2][4];
#pragma unroll
                for (int x = 0; x < 2; x++) {
                    const int ks = kp * 2 + x;
                    const int r = wq + (lane & 15);
                    const int c = ks * 2 + (lane >> 4);
                    const uint32_t off = r * 256 + (((uint32_t)(c ^ (r & 7))) << 4);
                    ldsm4(ah[x][0], ah[x][1], ah[x][2], ah[x][3], sQh + off);
                }
#pragma unroll
                for (int nt = 0; nt < 8; nt++) {
                    const int r = nt * 8 + (lane & 7);
                    const int c = kp * 4 + (lane >> 3);
                    const uint32_t off = r * 256 + (((uint32_t)(c ^ (r & 7))) << 4);
                    uint32_t kh[4];
                    ldsm4(kh[0], kh[1], kh[2], kh[3], st + off);
                    mma16816(S[nt], ah[0], kh[0], kh[1]);
                    mma16816(S[nt], ah[1], kh[2], kh[3]);
                }
            }

            if (j0 + 63 > q0 + wq) {
                const int row0 = q0 + wq + (lane >> 2), row1 = row0 + 8;
#pragma unroll
                for (int nt = 0; nt < 8; nt++) {
                    const int cb = j0 + nt * 8 + 2 * (lane & 3);
                    if (cb     > row0) S[nt][0] = -1e30f;
                    if (cb + 1 > row0) S[nt][1] = -1e30f;
                    if (cb     > row1) S[nt][2] = -1e30f;
                    if (cb + 1 > row1) S[nt][3] = -1e30f;
                }
            }

            float tm0 = -1e30f, tm1 = -1e30f;
#pragma unroll
            for (int nt = 0; nt < 8; nt++) {
                tm0 = fmaxf(tm0, fmaxf(S[nt][0], S[nt][1]));
                tm1 = fmaxf(tm1, fmaxf(S[nt][2], S[nt][3]));
            }
            tm0 = fmaxf(tm0, __shfl_xor_sync(0xffffffffu, tm0, 1));
            tm0 = fmaxf(tm0, __shfl_xor_sync(0xffffffffu, tm0, 2));
            tm1 = fmaxf(tm1, __shfl_xor_sync(0xffffffffu, tm1, 1));
            tm1 = fmaxf(tm1, __shfl_xor_sync(0xffffffffu, tm1, 2));
            const float mn0 = fmaxf(m0, tm0), mn1 = fmaxf(m1, tm1);
            const float cr0 = __expf((m0 - mn0) * scale);
            const float cr1 = __expf((m1 - mn1) * scale);
            m0 = mn0; m1 = mn1;

            uint32_t ph[8][2];
            float ps0 = 0.0f, ps1 = 0.0f;
#pragma unroll
            for (int nt = 0; nt < 8; nt++) {
                const float p0 = __expf((S[nt][0] - mn0) * scale);
                const float p1 = __expf((S[nt][1] - mn0) * scale);
                const float p2 = __expf((S[nt][2] - mn1) * scale);
                const float p3 = __expf((S[nt][3] - mn1) * scale);
                const __half h0 = __float2half_rn(p0), h1 = __float2half_rn(p1);
                const __half h2 = __float2half_rn(p2), h3 = __float2half_rn(p3);
                ps0 += __half2float(h0) + __half2float(h1);
                ps1 += __half2float(h2) + __half2float(h3);
                __half2 a01 = __halves2half2(h0, h1), a23 = __halves2half2(h2, h3);
                ph[nt][0] = *(uint32_t*)&a01;  ph[nt][1] = *(uint32_t*)&a23;
            }
            ps0 += __shfl_xor_sync(0xffffffffu, ps0, 1);
            ps0 += __shfl_xor_sync(0xffffffffu, ps0, 2);
            ps1 += __shfl_xor_sync(0xffffffffu, ps1, 1);
            ps1 += __shfl_xor_sync(0xffffffffu, ps1, 2);
            l0 = l0 * cr0 + ps0;
            l1 = l1 * cr1 + ps1;
#pragma unroll
            for (int nt = 0; nt < 16; nt++) {
                O[nt][0] *= cr0; O[nt][1] *= cr0;
                O[nt][2] *= cr1; O[nt][3] *= cr1;
            }

#pragma unroll
            for (int kt = 0; kt < 4; kt++) {
                uint32_t pah[4];
                pah[0] = ph[2 * kt][0];     pah[1] = ph[2 * kt][1];
                pah[2] = ph[2 * kt + 1][0]; pah[3] = ph[2 * kt + 1][1];
#pragma unroll
                for (int np = 0; np < 8; np++) {
                    const int r = kt * 16 + (lane & 15);
                    const int c = np * 2 + (lane >> 4);
                    const uint32_t off = r * 256 + (((uint32_t)(c ^ (r & 7))) << 4);
                    uint32_t vh[4];
                    ldsm4t(vh[0], vh[1], vh[2], vh[3], st + FA_KVT + off);
                    mma16816(O[2 * np],     pah, vh[0], vh[1]);
                    mma16816(O[2 * np + 1], pah, vh[2], vh[3]);
                }
            }
        }
        __syncthreads();
    }

    const float i0 = 1.0f / l0, i1 = 1.0f / l1;
    const int t0 = b * SEQL + q0 + wq + (lane >> 2);
#pragma unroll
    for (int nt = 0; nt < 16; nt++) {
        const int col = h * DHEAD + nt * 8 + 2 * (lane & 3);
        *(__half2*)&Ohi[(size_t)t0 * KDIM + col] =
            __floats2half2_rn(O[nt][0] * i0, O[nt][1] * i0);
        *(__half2*)&Ohi[(size_t)(t0 + 8) * KDIM + col] =
            __floats2half2_rn(O[nt][2] * i1, O[nt][3] * i1);
    }
}

// ---------------------------------------------------------------------------
extern "C" void kernel_launch(void* const* d_in, const int* in_sizes, int n_in,
                              void* d_out, int out_size)
{
    const float* x   = (const float*)d_in[0];
    // d_in[1] = mask: causal structure applied analytically, not read.
    const float* q_w = (const float*)d_in[2];
    const float* q_b = (const float*)d_in[3];
    const float* k_w = (const float*)d_in[4];
    const float* k_b = (const float*)d_in[5];
    const float* v_w = (const float*)d_in[6];
    const float* v_b = (const float*)d_in[7];
    const float* o_w = (const float*)d_in[8];
    const float* o_b = (const float*)d_in[9];
    float* out = (float*)d_out;

    __half *xh, *xl, *wqh, *wkh, *wvh, *woh;
    __half *qh, *kh, *vh, *ah;
    cudaGetSymbolAddress((void**)&xh, g_Xhi);   cudaGetSymbolAddress((void**)&xl, g_Xlo);
    cudaGetSymbolAddress((void**)&wqh, g_Wqh);
    cudaGetSymbolAddress((void**)&wkh, g_Wkh);
    cudaGetSymbolAddress((void**)&wvh, g_Wvh);
    cudaGetSymbolAddress((void**)&woh, g_Woh);
    cudaGetSymbolAddress((void**)&qh, g_Qh);
    cudaGetSymbolAddress((void**)&kh, g_Kh2);
    cudaGetSymbolAddress((void**)&vh, g_Vh2);
    cudaGetSymbolAddress((void**)&ah, g_Ahi);

    cudaFuncSetAttribute(qkv_proj, cudaFuncAttributeMaxDynamicSharedMemorySize,
                         QKV_SMEM);                        // 196608 (KC=128)
    cudaFuncSetAttribute(o_proj, cudaFuncAttributeMaxDynamicSharedMemorySize,
                         OPJ_SMEM);                        // 65536
    cudaFuncSetAttribute(flash_hmma, cudaFuncAttributeMaxDynamicSharedMemorySize,
                         FA_SMEM);

    const float WS = 1024.0f;
    dim3 blk(256);

    // Fused splits: x hi/lo + all weights hi, one launch
    split_all<<<SPLIT_BLOCKS, 256>>>(x, q_w, k_w, v_w, o_w,
                                     xh, xl, wqh, wkh, wvh, woh, WS);

    // Fused Q/K/V projections (split-2, KC=128)
    qkv_proj<<<dim3(48, 32), blk, QKV_SMEM>>>(xh, xl, wqh, wkh, wvh,
                                              q_b, k_b, v_b, qh, kh, vh);

    // Attention
    flash_hmma<<<dim3(SEQL / 128, NHEAD, NBATCH), blk, FA_SMEM>>>(qh, kh, vh, ah);

    // Output projection (pure fp16, 2 CTAs/SM)
    o_proj<<<dim3(32, 32), blk, OPJ_SMEM>>>(ah, woh, o_b, out);
}